// round 1
// baseline (speedup 1.0000x reference)
#include <cuda_runtime.h>
#include <math.h>

#define B_ 64
#define F_ 32
#define S_ 512
#define P_ 96
#define E_ 8
#define H_ 2048
#define T_ (F_*B_)   /* 2048 tokens */
#define ALPHA 10.0f
#define ENT_EPS 1e-8f
#define CV_EPS 1e-10f
#define KSPLIT 4

// ---- scratch (device globals: allocation-free) ----
__device__ float g_xf[(size_t)T_ * S_];                       // 4 MB  token-major x
__device__ float g_gates[T_ * E_];                            // 64 KB gates[f*B+b][e]
__device__ float g_h[(size_t)E_ * T_ * H_];                   // 134 MB gelu(x@W1+b1)
__device__ float g_eo[(size_t)E_ * KSPLIT * T_ * P_];         // 25 MB  partial expert outs

// ------------------------------------------------------------------
// 1) transpose x[b][f][s] -> g_xf[t][s], t = f*B + b
// ------------------------------------------------------------------
__global__ void prep_xf_kernel(const float* __restrict__ x) {
    int t = blockIdx.x;
    int f = t / B_, b = t - f * B_;
    const float4* src = (const float4*)(x + ((size_t)b * F_ + f) * S_);
    float4* dst = (float4*)(g_xf + (size_t)t * S_);
    dst[threadIdx.x] = src[threadIdx.x];          // 128 threads * float4 = 512 floats
}

// ------------------------------------------------------------------
// 2) gating network: one block per token, one warp per expert
// ------------------------------------------------------------------
__global__ void gates_kernel(const float* __restrict__ te,
                             const float* __restrict__ Wg,
                             const float* __restrict__ bg) {
    int t = blockIdx.x;
    int f = t / B_, b = t - f * B_;
    __shared__ float srow[S_];
    __shared__ float slog[E_];
    const float* row = te + ((size_t)b * F_ + f) * S_;
    for (int s = threadIdx.x; s < S_; s += 256) srow[s] = row[s];
    __syncthreads();

    int w = threadIdx.x >> 5, lane = threadIdx.x & 31;   // 8 warps = 8 experts
    float acc = 0.f;
    for (int s = lane; s < S_; s += 32) acc += srow[s] * Wg[s * E_ + w];
    #pragma unroll
    for (int o = 16; o > 0; o >>= 1) acc += __shfl_down_sync(0xffffffffu, acc, o);
    if (lane == 0) slog[w] = acc + bg[w];
    __syncthreads();

    if (threadIdx.x == 0) {
        float lg[E_];
        float m1 = -1e30f, m2 = -1e30f;
        #pragma unroll
        for (int i = 0; i < E_; i++) {
            float v = slog[i]; lg[i] = v;
            if (v > m1) { m2 = m1; m1 = v; } else if (v > m2) m2 = v;
        }
        float kth = m2;  // 2nd largest (TOP_K = 2)
        float sm[E_]; float se = 0.f;
        #pragma unroll
        for (int i = 0; i < E_; i++) { sm[i] = expf(lg[i] - m1); se += sm[i]; }
        float inv = 1.f / se;
        float dec[E_]; float mx2 = -1e30f;
        #pragma unroll
        for (int i = 0; i < E_; i++) {
            float smi = sm[i] * inv;
            float d = (lg[i] < kth) ? ALPHA * logf(smi + 1.f)
                                    : ALPHA * (expf(smi) - 1.f);
            dec[i] = d; if (d > mx2) mx2 = d;
        }
        float s2 = 0.f;
        #pragma unroll
        for (int i = 0; i < E_; i++) { dec[i] = expf(dec[i] - mx2); s2 += dec[i]; }
        float inv2 = 1.f / s2;
        #pragma unroll
        for (int i = 0; i < E_; i++) g_gates[t * E_ + i] = dec[i] * inv2;
    }
}

// ------------------------------------------------------------------
// 3) losses: single block. gsum[f][e] over batch, then cv / entropy
// ------------------------------------------------------------------
__global__ void losses_kernel(float* __restrict__ out_scalars) {
    __shared__ float gsum[F_][E_];
    __shared__ float cvf[F_], entf[F_];
    int tid = threadIdx.x;                       // 256 = 32*8
    int f = tid >> 3, e = tid & 7;
    float s = 0.f;
    for (int b = 0; b < B_; b++) s += g_gates[(f * B_ + b) * E_ + e];
    gsum[f][e] = s;
    __syncthreads();
    if (tid < F_) {
        float mean = 0.f;
        #pragma unroll
        for (int i = 0; i < E_; i++) mean += gsum[tid][i];
        mean *= (1.f / E_);
        float ss = 0.f;
        #pragma unroll
        for (int i = 0; i < E_; i++) { float d = gsum[tid][i] - mean; ss += d * d; }
        float var = ss * (float)P_ / (float)(E_ * P_ - 1);   // ddof=1 over E*P repeats
        cvf[tid] = var / (mean * mean + CV_EPS);
        float ent = 0.f;
        #pragma unroll
        for (int i = 0; i < E_; i++) {
            float g = gsum[tid][i] * (1.f / B_);
            ent += -g * logf(g + ENT_EPS);
        }
        entf[tid] = ent * (1.f / E_);
    }
    __syncthreads();
    if (tid == 0) {
        float a = 0.f, c = 0.f;
        for (int i = 0; i < F_; i++) { a += cvf[i]; c += entf[i]; }
        out_scalars[0] = a;   // selector_loss
        out_scalars[1] = c;   // entropy_loss
    }
}

// ------------------------------------------------------------------
// 4) GEMM1: h[e] = gelu(Xf @ W1[e] + b1[e])   M=2048 N=2048 K=512
//    128x128x8 tile, 8x8 microtile, 256 thr, double-buffered smem
// ------------------------------------------------------------------
__global__ void __launch_bounds__(256, 2) gemm1_kernel(const float* __restrict__ W1,
                                                       const float* __restrict__ b1) {
    const int e = blockIdx.z;
    const int bm = blockIdx.y * 128;
    const int bn = blockIdx.x * 128;
    const float* A = g_xf;
    const float* Bm = W1 + (size_t)e * S_ * H_;
    const float* bias = b1 + e * H_;
    float* C = g_h + (size_t)e * T_ * H_;

    __shared__ float As[2][8][128];
    __shared__ float Bs[2][8][128];

    const int tid = threadIdx.x;
    const int a_row = tid >> 1;
    const int a_col = (tid & 1) << 2;
    const int b_row = tid >> 5;
    const int b_col = (tid & 31) << 2;
    const int ty = tid >> 4;
    const int tx = tid & 15;

    float acc[8][8];
    #pragma unroll
    for (int i = 0; i < 8; i++)
        #pragma unroll
        for (int j = 0; j < 8; j++) acc[i][j] = 0.f;

    const float* aptr = A + (size_t)(bm + a_row) * S_ + a_col;
    const float* bptr = Bm + (size_t)b_row * H_ + bn + b_col;

    float4 a4 = *(const float4*)aptr;
    float4 b4 = *(const float4*)bptr;
    As[0][a_col + 0][a_row] = a4.x;
    As[0][a_col + 1][a_row] = a4.y;
    As[0][a_col + 2][a_row] = a4.z;
    As[0][a_col + 3][a_row] = a4.w;
    *(float4*)&Bs[0][b_row][b_col] = b4;
    __syncthreads();

    int buf = 0;
    const int NKT = S_ / 8;          // 64
    for (int kt = 0; kt < NKT; kt++) {
        if (kt + 1 < NKT) {
            a4 = *(const float4*)(aptr + (kt + 1) * 8);
            b4 = *(const float4*)(bptr + (size_t)(kt + 1) * 8 * H_);
        }
        #pragma unroll
        for (int k = 0; k < 8; k++) {
            float ar[8], br[8];
            *(float4*)&ar[0] = *(const float4*)&As[buf][k][ty * 8];
            *(float4*)&ar[4] = *(const float4*)&As[buf][k][ty * 8 + 4];
            *(float4*)&br[0] = *(const float4*)&Bs[buf][k][tx * 8];
            *(float4*)&br[4] = *(const float4*)&Bs[buf][k][tx * 8 + 4];
            #pragma unroll
            for (int i = 0; i < 8; i++)
                #pragma unroll
                for (int j = 0; j < 8; j++)
                    acc[i][j] += ar[i] * br[j];
        }
        if (kt + 1 < NKT) {
            buf ^= 1;
            As[buf][a_col + 0][a_row] = a4.x;
            As[buf][a_col + 1][a_row] = a4.y;
            As[buf][a_col + 2][a_row] = a4.z;
            As[buf][a_col + 3][a_row] = a4.w;
            *(float4*)&Bs[buf][b_row][b_col] = b4;
            __syncthreads();
        }
    }

    float bv[8];
    *(float4*)&bv[0] = *(const float4*)&bias[bn + tx * 8];
    *(float4*)&bv[4] = *(const float4*)&bias[bn + tx * 8 + 4];

    #pragma unroll
    for (int i = 0; i < 8; i++) {
        float* crow = C + (size_t)(bm + ty * 8 + i) * H_ + bn + tx * 8;
        #pragma unroll
        for (int jj = 0; jj < 8; jj += 4) {
            float4 o;
            float v0 = acc[i][jj + 0] + bv[jj + 0];
            float v1 = acc[i][jj + 1] + bv[jj + 1];
            float v2 = acc[i][jj + 2] + bv[jj + 2];
            float v3 = acc[i][jj + 3] + bv[jj + 3];
            o.x = 0.5f * v0 * (1.f + erff(v0 * 0.70710678118f));
            o.y = 0.5f * v1 * (1.f + erff(v1 * 0.70710678118f));
            o.z = 0.5f * v2 * (1.f + erff(v2 * 0.70710678118f));
            o.w = 0.5f * v3 * (1.f + erff(v3 * 0.70710678118f));
            *(float4*)(crow + jj) = o;
        }
    }
}

// ------------------------------------------------------------------
// 5) GEMM2 (K-split): eo[e][ks] = h[e][:, ks*512:(ks+1)*512] @ W2[e][...]
//    M=2048 N=96 Kchunk=512. 128x96x8 tile, 8x6 microtile, 256 thr.
// ------------------------------------------------------------------
__global__ void __launch_bounds__(256, 2) gemm2_kernel(const float* __restrict__ W2) {
    const int ks = blockIdx.x;
    const int bm = blockIdx.y * 128;
    const int e = blockIdx.z;
    const int k_base = ks * (H_ / KSPLIT);
    const float* A = g_h + (size_t)e * T_ * H_;
    const float* Bm = W2 + (size_t)e * H_ * P_;
    float* C = g_eo + (size_t)(e * KSPLIT + ks) * T_ * P_;

    __shared__ float As[2][8][128];
    __shared__ float Bs[2][8][96];

    const int tid = threadIdx.x;
    const int a_row = tid >> 1;
    const int a_col = (tid & 1) << 2;
    const int ty = tid >> 4;
    const int tx = tid & 15;

    const int b_r = tid / 24;
    const int b_c = (tid % 24) * 4;
    const bool bload = tid < 192;

    float acc[8][6];
    #pragma unroll
    for (int i = 0; i < 8; i++)
        #pragma unroll
        for (int j = 0; j < 6; j++) acc[i][j] = 0.f;

    const float* aptr = A + (size_t)(bm + a_row) * H_ + k_base + a_col;
    const float* bptr = Bm + (size_t)(k_base + b_r) * P_ + b_c;

    float4 a4 = *(const float4*)aptr;
    float4 b4 = make_float4(0.f, 0.f, 0.f, 0.f);
    if (bload) b4 = *(const float4*)bptr;
    As[0][a_col + 0][a_row] = a4.x;
    As[0][a_col + 1][a_row] = a4.y;
    As[0][a_col + 2][a_row] = a4.z;
    As[0][a_col + 3][a_row] = a4.w;
    if (bload) *(float4*)&Bs[0][b_r][b_c] = b4;
    __syncthreads();

    int buf = 0;
    const int NKT = (H_ / KSPLIT) / 8;   // 64
    for (int kt = 0; kt < NKT; kt++) {
        if (kt + 1 < NKT) {
            a4 = *(const float4*)(aptr + (kt + 1) * 8);
            if (bload) b4 = *(const float4*)(bptr + (size_t)(kt + 1) * 8 * P_);
        }
        #pragma unroll
        for (int k = 0; k < 8; k++) {
            float ar[8], br[6];
            *(float4*)&ar[0] = *(const float4*)&As[buf][k][ty * 8];
            *(float4*)&ar[4] = *(const float4*)&As[buf][k][ty * 8 + 4];
            *(float2*)&br[0] = *(const float2*)&Bs[buf][k][tx * 6];
            *(float2*)&br[2] = *(const float2*)&Bs[buf][k][tx * 6 + 2];
            *(float2*)&br[4] = *(const float2*)&Bs[buf][k][tx * 6 + 4];
            #pragma unroll
            for (int i = 0; i < 8; i++)
                #pragma unroll
                for (int j = 0; j < 6; j++)
                    acc[i][j] += ar[i] * br[j];
        }
        if (kt + 1 < NKT) {
            buf ^= 1;
            As[buf][a_col + 0][a_row] = a4.x;
            As[buf][a_col + 1][a_row] = a4.y;
            As[buf][a_col + 2][a_row] = a4.z;
            As[buf][a_col + 3][a_row] = a4.w;
            if (bload) *(float4*)&Bs[buf][b_r][b_c] = b4;
            __syncthreads();
        }
    }

    #pragma unroll
    for (int i = 0; i < 8; i++) {
        float* crow = C + (size_t)(bm + ty * 8 + i) * P_ + tx * 6;
        #pragma unroll
        for (int j = 0; j < 6; j++) crow[j] = acc[i][j];
    }
}

// ------------------------------------------------------------------
// 6) combine: out[b][f][p] = sum_e gates[t][e] * (sum_ks eo + b2[e][p])
// ------------------------------------------------------------------
__global__ void combine_kernel(const float* __restrict__ b2, float* __restrict__ out) {
    int idx = blockIdx.x * blockDim.x + threadIdx.x;
    if (idx >= T_ * P_) return;
    int t = idx / P_, p = idx - t * P_;
    int f = t / B_, b = t - f * B_;
    float r = 0.f;
    #pragma unroll
    for (int e = 0; e < E_; e++) {
        float v = b2[e * P_ + p];
        #pragma unroll
        for (int ks = 0; ks < KSPLIT; ks++)
            v += g_eo[((size_t)(e * KSPLIT + ks) * T_ + t) * P_ + p];
        r += g_gates[t * E_ + e] * v;
    }
    out[((size_t)b * F_ + f) * P_ + p] = r;
}

// ------------------------------------------------------------------
extern "C" void kernel_launch(void* const* d_in, const int* in_sizes, int n_in,
                              void* d_out, int out_size) {
    const float* x  = (const float*)d_in[0];
    const float* te = (const float*)d_in[1];
    const float* Wg = (const float*)d_in[2];
    const float* bg = (const float*)d_in[3];
    const float* W1 = (const float*)d_in[4];
    const float* b1 = (const float*)d_in[5];
    const float* W2 = (const float*)d_in[6];
    const float* b2 = (const float*)d_in[7];
    float* out = (float*)d_out;

    prep_xf_kernel<<<T_, 128>>>(x);
    gates_kernel<<<T_, 256>>>(te, Wg, bg);
    losses_kernel<<<1, 256>>>(out + (out_size - 2));
    gemm1_kernel<<<dim3(H_ / 128, T_ / 128, E_), 256>>>(W1, b1);
    gemm2_kernel<<<dim3(KSPLIT, T_ / 128, E_), 256>>>(W2);
    combine_kernel<<<(T_ * P_ + 255) / 256, 256>>>(b2, out);
}

// round 3
// speedup vs baseline: 2.8043x; 2.8043x over previous
#include <cuda_runtime.h>
#include <math.h>
#include <stdint.h>

#define B_ 64
#define F_ 32
#define S_ 512
#define P_ 96
#define E_ 8
#define H_ 2048
#define T_ (F_*B_)   /* 2048 tokens */
#define ALPHA 10.0f
#define ENT_EPS 1e-8f
#define CV_EPS 1e-10f

// ---- scratch (device globals: allocation-free) ----
__device__ float g_xf[(size_t)T_ * S_];            // 4 MB   token-major x (tf32-rounded)
__device__ float g_w1t[(size_t)E_ * H_ * S_];      // 33.5MB W1^T [e][h][s] (tf32)
__device__ float g_w2t[(size_t)E_ * P_ * H_];      // 6.3 MB W2^T [e][p][h] (tf32)
__device__ float g_gates[T_ * E_];                 // 64 KB
__device__ float g_h[(size_t)E_ * T_ * H_];        // 134 MB gelu(x@W1+b1)  (tf32)
__device__ float g_eo[(size_t)E_ * T_ * P_];       // 6.3 MB expert outputs (fp32)

// ==================================================================
// helpers
// ==================================================================
__device__ __forceinline__ uint32_t smem_u32(const void* p) {
    uint32_t a;
    asm("{ .reg .u64 t; cvta.to.shared.u64 t, %1; cvt.u32.u64 %0, t; }"
        : "=r"(a) : "l"(p));
    return a;
}
__device__ __forceinline__ uint32_t tf32r(float f) {   // round-to-nearest tf32 bits
    uint32_t r;
    asm("cvt.rna.tf32.f32 %0, %1;" : "=r"(r) : "f"(f));
    return r;
}
__device__ __forceinline__ float tf32f(float f) { return __uint_as_float(tf32r(f)); }
__device__ __forceinline__ void cp16(uint32_t saddr, const void* gaddr) {
    asm volatile("cp.async.cg.shared.global [%0], [%1], 16;"
                 :: "r"(saddr), "l"(gaddr) : "memory");
}
#define CP_COMMIT() asm volatile("cp.async.commit_group;" ::: "memory")
#define CP_WAIT2()  asm volatile("cp.async.wait_group 2;" ::: "memory")

__device__ __forceinline__ void mma8(float* d, const uint32_t* a, const uint32_t* b) {
    asm volatile(
        "mma.sync.aligned.m16n8k8.row.col.f32.tf32.tf32.f32 "
        "{%0,%1,%2,%3}, {%4,%5,%6,%7}, {%8,%9}, {%0,%1,%2,%3};"
        : "+f"(d[0]), "+f"(d[1]), "+f"(d[2]), "+f"(d[3])
        : "r"(a[0]), "r"(a[1]), "r"(a[2]), "r"(a[3]), "r"(b[0]), "r"(b[1]));
}
__device__ __forceinline__ float gelu_f(float v) {
    return 0.5f * v * (1.f + erff(v * 0.70710678118f));
}

// ==================================================================
// 1) transpose x[b][f][s] -> g_xf[t][s] (tf32-rounded)
// ==================================================================
__global__ void prep_xf_kernel(const float* __restrict__ x) {
    int t = blockIdx.x;
    int f = t / B_, b = t - f * B_;
    const float4* src = (const float4*)(x + ((size_t)b * F_ + f) * S_);
    float4* dst = (float4*)(g_xf + (size_t)t * S_);
    float4 v = src[threadIdx.x];
    v.x = tf32f(v.x); v.y = tf32f(v.y); v.z = tf32f(v.z); v.w = tf32f(v.w);
    dst[threadIdx.x] = v;
}

// ==================================================================
// 1b) W1 [e][s][h] -> g_w1t [e][h][s];  W2 [e][h][p] -> g_w2t [e][p][h]
//     (tf32-rounded on store)
// ==================================================================
__global__ void transpose_w1_kernel(const float* __restrict__ W1) {
    __shared__ float tile[32][33];
    int e = blockIdx.z;
    int h0 = blockIdx.x * 32, s0 = blockIdx.y * 32;
    int lx = threadIdx.x, ly = threadIdx.y;          // 32 x 8
    #pragma unroll
    for (int i = 0; i < 32; i += 8)
        tile[ly + i][lx] = W1[((size_t)e * S_ + s0 + ly + i) * H_ + h0 + lx];
    __syncthreads();
    #pragma unroll
    for (int i = 0; i < 32; i += 8)
        g_w1t[((size_t)e * H_ + h0 + ly + i) * S_ + s0 + lx] = tf32f(tile[lx][ly + i]);
}
__global__ void transpose_w2_kernel(const float* __restrict__ W2) {
    __shared__ float tile[32][33];
    int e = blockIdx.z;
    int p0 = blockIdx.x * 32, h0 = blockIdx.y * 32;
    int lx = threadIdx.x, ly = threadIdx.y;
    #pragma unroll
    for (int i = 0; i < 32; i += 8)
        tile[ly + i][lx] = W2[((size_t)e * H_ + h0 + ly + i) * P_ + p0 + lx];
    __syncthreads();
    #pragma unroll
    for (int i = 0; i < 32; i += 8)
        g_w2t[((size_t)e * P_ + p0 + ly + i) * H_ + h0 + lx] = tf32f(tile[lx][ly + i]);
}

// ==================================================================
// 2) gating network (exact fp32)
// ==================================================================
__global__ void gates_kernel(const float* __restrict__ te,
                             const float* __restrict__ Wg,
                             const float* __restrict__ bg) {
    int t = blockIdx.x;
    int f = t / B_, b = t - f * B_;
    __shared__ float srow[S_];
    __shared__ float slog[E_];
    const float* row = te + ((size_t)b * F_ + f) * S_;
    for (int s = threadIdx.x; s < S_; s += 256) srow[s] = row[s];
    __syncthreads();

    int w = threadIdx.x >> 5, lane = threadIdx.x & 31;
    float acc = 0.f;
    for (int s = lane; s < S_; s += 32) acc += srow[s] * Wg[s * E_ + w];
    #pragma unroll
    for (int o = 16; o > 0; o >>= 1) acc += __shfl_down_sync(0xffffffffu, acc, o);
    if (lane == 0) slog[w] = acc + bg[w];
    __syncthreads();

    if (threadIdx.x == 0) {
        float lg[E_];
        float m1 = -1e30f, m2 = -1e30f;
        #pragma unroll
        for (int i = 0; i < E_; i++) {
            float v = slog[i]; lg[i] = v;
            if (v > m1) { m2 = m1; m1 = v; } else if (v > m2) m2 = v;
        }
        float kth = m2;
        float sm[E_]; float se = 0.f;
        #pragma unroll
        for (int i = 0; i < E_; i++) { sm[i] = expf(lg[i] - m1); se += sm[i]; }
        float inv = 1.f / se;
        float dec[E_]; float mx2 = -1e30f;
        #pragma unroll
        for (int i = 0; i < E_; i++) {
            float smi = sm[i] * inv;
            float d = (lg[i] < kth) ? ALPHA * logf(smi + 1.f)
                                    : ALPHA * (expf(smi) - 1.f);
            dec[i] = d; if (d > mx2) mx2 = d;
        }
        float s2 = 0.f;
        #pragma unroll
        for (int i = 0; i < E_; i++) { dec[i] = expf(dec[i] - mx2); s2 += dec[i]; }
        float inv2 = 1.f / s2;
        #pragma unroll
        for (int i = 0; i < E_; i++) g_gates[t * E_ + i] = dec[i] * inv2;
    }
}

// ==================================================================
// 3) losses (exact fp32)
// ==================================================================
__global__ void losses_kernel(float* __restrict__ out_scalars) {
    __shared__ float gsum[F_][E_];
    __shared__ float cvf[F_], entf[F_];
    int tid = threadIdx.x;
    int f = tid >> 3, e = tid & 7;
    float s = 0.f;
    for (int b = 0; b < B_; b++) s += g_gates[(f * B_ + b) * E_ + e];
    gsum[f][e] = s;
    __syncthreads();
    if (tid < F_) {
        float mean = 0.f;
        #pragma unroll
        for (int i = 0; i < E_; i++) mean += gsum[tid][i];
        mean *= (1.f / E_);
        float ss = 0.f;
        #pragma unroll
        for (int i = 0; i < E_; i++) { float d = gsum[tid][i] - mean; ss += d * d; }
        float var = ss * (float)P_ / (float)(E_ * P_ - 1);
        cvf[tid] = var / (mean * mean + CV_EPS);
        float ent = 0.f;
        #pragma unroll
        for (int i = 0; i < E_; i++) {
            float g = gsum[tid][i] * (1.f / B_);
            ent += -g * logf(g + ENT_EPS);
        }
        entf[tid] = ent * (1.f / E_);
    }
    __syncthreads();
    if (tid == 0) {
        float a = 0.f, c = 0.f;
        for (int i = 0; i < F_; i++) { a += cvf[i]; c += entf[i]; }
        out_scalars[0] = a;
        out_scalars[1] = c;
    }
}

// ==================================================================
// 4) GEMM1 (mma.sync tf32):  h = gelu(Xf @ W1t^T + b1),  tf32-rounded store
//    block 256M x 128N x 32K, 3-stage cp.async, 8 warps, warp tile 64x64
//    smem rows padded to 36 floats (conflict-free frags: 36 mod 32 = 4)
// ==================================================================
#define G1_STAGE_F 13824      /* (256+128)*36 floats */
#define G1_B_OFF_F 9216       /* 256*36 */
#define G1_SMEM (3 * G1_STAGE_F * 4)
__global__ void __launch_bounds__(256, 1) gemm1_tc(const float* __restrict__ b1) {
    extern __shared__ float smx[];
    const int tid = threadIdx.x;
    const int wid = tid >> 5, lane = tid & 31;
    const int g = lane >> 2, tg = lane & 3;
    const int e = blockIdx.z;
    const int bm = blockIdx.y * 256, bn = blockIdx.x * 128;
    const int wm = (wid & 3) * 64, wn = (wid >> 2) * 64;
    const uint32_t smb = smem_u32(smx);

    const float* gA = g_xf + (size_t)bm * S_;
    const float* gB = g_w1t + ((size_t)e * H_ + bn) * S_;

    float acc[4][8][4];
    #pragma unroll
    for (int i = 0; i < 4; i++)
        #pragma unroll
        for (int j = 0; j < 8; j++)
            #pragma unroll
            for (int c = 0; c < 4; c++) acc[i][j][c] = 0.f;

    auto load_stage = [&](int kt, int buf) {
        const uint32_t sA = smb + (uint32_t)buf * (G1_STAGE_F * 4);
        const uint32_t sB = sA + G1_B_OFF_F * 4;
        const int k0 = kt * 32;
        #pragma unroll
        for (int i = 0; i < 8; i++) {          // A: 256 rows x 8 xfloat4
            int idx = tid + 256 * i;
            int r = idx >> 3, q = idx & 7;
            cp16(sA + (uint32_t)r * 144u + (uint32_t)q * 16u,
                 gA + (size_t)r * S_ + k0 + q * 4);
        }
        #pragma unroll
        for (int i = 0; i < 4; i++) {          // B: 128 rows
            int idx = tid + 256 * i;
            int r = idx >> 3, q = idx & 7;
            cp16(sB + (uint32_t)r * 144u + (uint32_t)q * 16u,
                 gB + (size_t)r * S_ + k0 + q * 4);
        }
    };

    const int NKT = S_ / 32;   // 16
    #pragma unroll
    for (int s = 0; s < 3; s++) { load_stage(s, s); CP_COMMIT(); }

    for (int kt = 0; kt < NKT; kt++) {
        const int buf = kt % 3;
        CP_WAIT2();
        __syncthreads();
        const float* As = smx + buf * G1_STAGE_F;
        const float* Bs = As + G1_B_OFF_F;
        #pragma unroll
        for (int kk = 0; kk < 4; kk++) {
            const int kb = kk * 8;
            uint32_t a[4][4], b[8][2];
            #pragma unroll
            for (int i = 0; i < 4; i++) {
                int r = wm + i * 16 + g;
                a[i][0] = __float_as_uint(As[r * 36 + kb + tg]);
                a[i][1] = __float_as_uint(As[(r + 8) * 36 + kb + tg]);
                a[i][2] = __float_as_uint(As[r * 36 + kb + tg + 4]);
                a[i][3] = __float_as_uint(As[(r + 8) * 36 + kb + tg + 4]);
            }
            #pragma unroll
            for (int j = 0; j < 8; j++) {
                int n = wn + j * 8 + g;
                b[j][0] = __float_as_uint(Bs[n * 36 + kb + tg]);
                b[j][1] = __float_as_uint(Bs[n * 36 + kb + tg + 4]);
            }
            #pragma unroll
            for (int i = 0; i < 4; i++)
                #pragma unroll
                for (int j = 0; j < 8; j++)
                    mma8(acc[i][j], a[i], b[j]);
        }
        __syncthreads();
        if (kt + 3 < NKT) load_stage(kt + 3, buf);
        CP_COMMIT();
    }

    // epilogue: bias + exact gelu, tf32-rounded store
    const float* bias = b1 + (size_t)e * H_ + bn;
    #pragma unroll
    for (int i = 0; i < 4; i++) {
        int r0 = bm + wm + i * 16 + g;
        #pragma unroll
        for (int j = 0; j < 8; j++) {
            int col = wn + j * 8 + 2 * tg;
            float bx = bias[col], by = bias[col + 1];
            float2 o0, o1;
            o0.x = tf32f(gelu_f(acc[i][j][0] + bx));
            o0.y = tf32f(gelu_f(acc[i][j][1] + by));
            o1.x = tf32f(gelu_f(acc[i][j][2] + bx));
            o1.y = tf32f(gelu_f(acc[i][j][3] + by));
            *(float2*)(g_h + ((size_t)e * T_ + r0) * H_ + bn + col) = o0;
            *(float2*)(g_h + ((size_t)e * T_ + r0 + 8) * H_ + bn + col) = o1;
        }
    }
}

// ==================================================================
// 5) GEMM2 (mma.sync tf32):  eo = h @ W2t^T
//    block 128M x 96N x 32K, 3-stage, 8 warps, warp tile 32x48
// ==================================================================
#define G2_STAGE_F 8064       /* (128+96)*36 */
#define G2_B_OFF_F 4608       /* 128*36 */
#define G2_SMEM (3 * G2_STAGE_F * 4)
__global__ void __launch_bounds__(256, 1) gemm2_tc(void) {
    extern __shared__ float smx[];
    const int tid = threadIdx.x;
    const int wid = tid >> 5, lane = tid & 31;
    const int g = lane >> 2, tg = lane & 3;
    const int e = blockIdx.z;
    const int bm = blockIdx.y * 128;
    const int wm = (wid & 3) * 32, wn = (wid >> 2) * 48;
    const uint32_t smb = smem_u32(smx);

    const float* gA = g_h + ((size_t)e * T_ + bm) * H_;
    const float* gB = g_w2t + (size_t)e * P_ * H_;

    float acc[2][6][4];
    #pragma unroll
    for (int i = 0; i < 2; i++)
        #pragma unroll
        for (int j = 0; j < 6; j++)
            #pragma unroll
            for (int c = 0; c < 4; c++) acc[i][j][c] = 0.f;

    auto load_stage = [&](int kt, int buf) {
        const uint32_t sA = smb + (uint32_t)buf * (G2_STAGE_F * 4);
        const uint32_t sB = sA + G2_B_OFF_F * 4;
        const int k0 = kt * 32;
        #pragma unroll
        for (int i = 0; i < 4; i++) {          // A: 128 rows
            int idx = tid + 256 * i;
            int r = idx >> 3, q = idx & 7;
            cp16(sA + (uint32_t)r * 144u + (uint32_t)q * 16u,
                 gA + (size_t)r * H_ + k0 + q * 4);
        }
        #pragma unroll
        for (int i = 0; i < 3; i++) {          // B: 96 rows
            int idx = tid + 256 * i;
            int r = idx >> 3, q = idx & 7;
            cp16(sB + (uint32_t)r * 144u + (uint32_t)q * 16u,
                 gB + (size_t)r * H_ + k0 + q * 4);
        }
    };

    const int NKT = H_ / 32;   // 64
    #pragma unroll
    for (int s = 0; s < 3; s++) { load_stage(s, s); CP_COMMIT(); }

    for (int kt = 0; kt < NKT; kt++) {
        const int buf = kt % 3;
        CP_WAIT2();
        __syncthreads();
        const float* As = smx + buf * G2_STAGE_F;
        const float* Bs = As + G2_B_OFF_F;
        #pragma unroll
        for (int kk = 0; kk < 4; kk++) {
            const int kb = kk * 8;
            uint32_t a[2][4], b[6][2];
            #pragma unroll
            for (int i = 0; i < 2; i++) {
                int r = wm + i * 16 + g;
                a[i][0] = __float_as_uint(As[r * 36 + kb + tg]);
                a[i][1] = __float_as_uint(As[(r + 8) * 36 + kb + tg]);
                a[i][2] = __float_as_uint(As[r * 36 + kb + tg + 4]);
                a[i][3] = __float_as_uint(As[(r + 8) * 36 + kb + tg + 4]);
            }
            #pragma unroll
            for (int j = 0; j < 6; j++) {
                int n = wn + j * 8 + g;
                b[j][0] = __float_as_uint(Bs[n * 36 + kb + tg]);
                b[j][1] = __float_as_uint(Bs[n * 36 + kb + tg + 4]);
            }
            #pragma unroll
            for (int i = 0; i < 2; i++)
                #pragma unroll
                for (int j = 0; j < 6; j++)
                    mma8(acc[i][j], a[i], b[j]);
        }
        __syncthreads();
        if (kt + 3 < NKT) load_stage(kt + 3, buf);
        CP_COMMIT();
    }

    #pragma unroll
    for (int i = 0; i < 2; i++) {
        int r0 = bm + wm + i * 16 + g;
        #pragma unroll
        for (int j = 0; j < 6; j++) {
            int col = wn + j * 8 + 2 * tg;
            float2 o0, o1;
            o0.x = acc[i][j][0]; o0.y = acc[i][j][1];
            o1.x = acc[i][j][2]; o1.y = acc[i][j][3];
            *(float2*)(g_eo + ((size_t)e * T_ + r0) * P_ + col) = o0;
            *(float2*)(g_eo + ((size_t)e * T_ + r0 + 8) * P_ + col) = o1;
        }
    }
}

// ==================================================================
// 6) combine: out[b][f][p] = sum_e gates[t][e] * (eo[e][t][p] + b2[e][p])
// ==================================================================
__global__ void combine_kernel(const float* __restrict__ b2, float* __restrict__ out) {
    int idx = blockIdx.x * blockDim.x + threadIdx.x;
    if (idx >= T_ * P_) return;
    int t = idx / P_, p = idx - t * P_;
    int f = t / B_, b = t - f * B_;
    float r = 0.f;
    #pragma unroll
    for (int e = 0; e < E_; e++) {
        float v = b2[e * P_ + p] + g_eo[((size_t)e * T_ + t) * P_ + p];
        r += g_gates[t * E_ + e] * v;
    }
    out[((size_t)b * F_ + f) * P_ + p] = r;
}

// ==================================================================
extern "C" void kernel_launch(void* const* d_in, const int* in_sizes, int n_in,
                              void* d_out, int out_size) {
    const float* x  = (const float*)d_in[0];
    const float* te = (const float*)d_in[1];
    const float* Wg = (const float*)d_in[2];
    const float* bg = (const float*)d_in[3];
    const float* W1 = (const float*)d_in[4];
    const float* b1 = (const float*)d_in[5];
    const float* W2 = (const float*)d_in[6];
    const float* b2 = (const float*)d_in[7];
    float* out = (float*)d_out;

    cudaFuncSetAttribute(gemm1_tc, cudaFuncAttributeMaxDynamicSharedMemorySize, G1_SMEM);
    cudaFuncSetAttribute(gemm2_tc, cudaFuncAttributeMaxDynamicSharedMemorySize, G2_SMEM);

    prep_xf_kernel<<<T_, 128>>>(x);
    transpose_w1_kernel<<<dim3(H_ / 32, S_ / 32, E_), dim3(32, 8)>>>(W1);
    transpose_w2_kernel<<<dim3(P_ / 32, H_ / 32, E_), dim3(32, 8)>>>(W2);
    gates_kernel<<<T_, 256>>>(te, Wg, bg);
    losses_kernel<<<1, 256>>>(out + (out_size - 2));
    gemm1_tc<<<dim3(H_ / 128, T_ / 256, E_), 256, G1_SMEM>>>(b1);
    gemm2_tc<<<dim3(1, T_ / 128, E_), 256, G2_SMEM>>>();
    combine_kernel<<<(T_ * P_ + 255) / 256, 256>>>(b2, out);
}

// round 4
// speedup vs baseline: 3.9900x; 1.4228x over previous
#include <cuda_runtime.h>
#include <cuda_fp16.h>
#include <math.h>
#include <stdint.h>

#define B_ 64
#define F_ 32
#define S_ 512
#define P_ 96
#define E_ 8
#define H_ 2048
#define T_ (F_*B_)   /* 2048 tokens */
#define ALPHA 10.0f
#define ENT_EPS 1e-8f
#define CV_EPS 1e-10f

// ---- scratch (device globals: allocation-free) ----
__device__ __half g_xf[(size_t)T_ * S_];           // 2 MB   token-major x (fp16)
__device__ __half g_w1t[(size_t)E_ * H_ * S_];     // 16.8MB W1^T [e][h][s] (fp16)
__device__ __half g_w2t[(size_t)E_ * P_ * H_];     // 3.1 MB W2^T [e][p][h] (fp16)
__device__ float  g_wgt[E_ * S_];                  // 16 KB  Wg^T [e][s]
__device__ float  g_gates[T_ * E_];                // 64 KB
__device__ __half g_h[(size_t)E_ * T_ * H_];       // 67 MB  gelu(x@W1+b1) (fp16)
__device__ float  g_eo[(size_t)E_ * T_ * P_];      // 6.3 MB expert outputs (fp32)

// ==================================================================
// helpers
// ==================================================================
__device__ __forceinline__ uint32_t smem_u32(const void* p) {
    uint32_t a;
    asm("{ .reg .u64 t; cvta.to.shared.u64 t, %1; cvt.u32.u64 %0, t; }"
        : "=r"(a) : "l"(p));
    return a;
}
__device__ __forceinline__ void cp16(uint32_t saddr, const void* gaddr) {
    asm volatile("cp.async.cg.shared.global [%0], [%1], 16;"
                 :: "r"(saddr), "l"(gaddr) : "memory");
}
#define CP_COMMIT() asm volatile("cp.async.commit_group;" ::: "memory")
#define CP_WAIT2()  asm volatile("cp.async.wait_group 2;" ::: "memory")

// m16n8k16 fp16 mma, fp32 accumulate
__device__ __forceinline__ void mma16(float* d, const uint32_t* a, const uint32_t* b) {
    asm volatile(
        "mma.sync.aligned.m16n8k16.row.col.f32.f16.f16.f32 "
        "{%0,%1,%2,%3}, {%4,%5,%6,%7}, {%8,%9}, {%0,%1,%2,%3};"
        : "+f"(d[0]), "+f"(d[1]), "+f"(d[2]), "+f"(d[3])
        : "r"(a[0]), "r"(a[1]), "r"(a[2]), "r"(a[3]), "r"(b[0]), "r"(b[1]));
}
__device__ __forceinline__ float gelu_f(float v) {
    return 0.5f * v * (1.f + erff(v * 0.70710678118f));
}
__device__ __forceinline__ uint32_t lds32(const __half* base, int idx_halves) {
    return *(const uint32_t*)(base + idx_halves);
}

// smem pitch: 40 halves (80 B) per 32-half row -> conflict-free frag loads
#define PITCH 40

// ==================================================================
// 1) x[b][f][s] -> g_xf[t][s] fp16, t = f*B + b
// ==================================================================
__global__ void prep_xf_kernel(const float* __restrict__ x) {
    int t = blockIdx.x;
    int f = t / B_, b = t - f * B_;
    const float4* src = (const float4*)(x + ((size_t)b * F_ + f) * S_);
    float4 v = src[threadIdx.x];
    __half2* dst = (__half2*)(g_xf + (size_t)t * S_) + threadIdx.x * 2;
    dst[0] = __floats2half2_rn(v.x, v.y);
    dst[1] = __floats2half2_rn(v.z, v.w);
}

// ==================================================================
// 1b) weight transposes (fp16 out) + Wg^T (fp32)
// ==================================================================
__global__ void transpose_w1_kernel(const float* __restrict__ W1) {
    __shared__ float tile[32][33];
    int e = blockIdx.z;
    int h0 = blockIdx.x * 32, s0 = blockIdx.y * 32;
    int lx = threadIdx.x, ly = threadIdx.y;          // 32 x 8
    #pragma unroll
    for (int i = 0; i < 32; i += 8)
        tile[ly + i][lx] = W1[((size_t)e * S_ + s0 + ly + i) * H_ + h0 + lx];
    __syncthreads();
    #pragma unroll
    for (int i = 0; i < 32; i += 8)
        g_w1t[((size_t)e * H_ + h0 + ly + i) * S_ + s0 + lx] = __float2half_rn(tile[lx][ly + i]);
}
__global__ void transpose_w2_kernel(const float* __restrict__ W2) {
    __shared__ float tile[32][33];
    int e = blockIdx.z;
    int p0 = blockIdx.x * 32, h0 = blockIdx.y * 32;
    int lx = threadIdx.x, ly = threadIdx.y;
    #pragma unroll
    for (int i = 0; i < 32; i += 8)
        tile[ly + i][lx] = W2[((size_t)e * H_ + h0 + ly + i) * P_ + p0 + lx];
    __syncthreads();
    #pragma unroll
    for (int i = 0; i < 32; i += 8)
        g_w2t[((size_t)e * P_ + p0 + ly + i) * H_ + h0 + lx] = __float2half_rn(tile[lx][ly + i]);
}
__global__ void transpose_wg_kernel(const float* __restrict__ Wg) {
    int idx = blockIdx.x * 256 + threadIdx.x;        // 4096 total
    int e = idx >> 9, s = idx & 511;
    g_wgt[e * S_ + s] = Wg[s * E_ + e];
}

// ==================================================================
// 2) gating network (exact fp32) — coalesced Wg^T reads
// ==================================================================
__global__ void gates_kernel(const float* __restrict__ te,
                             const float* __restrict__ bg) {
    int t = blockIdx.x;
    int f = t / B_, b = t - f * B_;
    __shared__ float srow[S_];
    __shared__ float slog[E_];
    const float* row = te + ((size_t)b * F_ + f) * S_;
    for (int s = threadIdx.x; s < S_; s += 256) srow[s] = row[s];
    __syncthreads();

    int w = threadIdx.x >> 5, lane = threadIdx.x & 31;
    const float* wrow = g_wgt + w * S_;
    float acc = 0.f;
    for (int s = lane; s < S_; s += 32) acc += srow[s] * wrow[s];
    #pragma unroll
    for (int o = 16; o > 0; o >>= 1) acc += __shfl_down_sync(0xffffffffu, acc, o);
    if (lane == 0) slog[w] = acc + bg[w];
    __syncthreads();

    if (threadIdx.x == 0) {
        float lg[E_];
        float m1 = -1e30f, m2 = -1e30f;
        #pragma unroll
        for (int i = 0; i < E_; i++) {
            float v = slog[i]; lg[i] = v;
            if (v > m1) { m2 = m1; m1 = v; } else if (v > m2) m2 = v;
        }
        float kth = m2;
        float sm[E_]; float se = 0.f;
        #pragma unroll
        for (int i = 0; i < E_; i++) { sm[i] = expf(lg[i] - m1); se += sm[i]; }
        float inv = 1.f / se;
        float dec[E_]; float mx2 = -1e30f;
        #pragma unroll
        for (int i = 0; i < E_; i++) {
            float smi = sm[i] * inv;
            float d = (lg[i] < kth) ? ALPHA * logf(smi + 1.f)
                                    : ALPHA * (expf(smi) - 1.f);
            dec[i] = d; if (d > mx2) mx2 = d;
        }
        float s2 = 0.f;
        #pragma unroll
        for (int i = 0; i < E_; i++) { dec[i] = expf(dec[i] - mx2); s2 += dec[i]; }
        float inv2 = 1.f / s2;
        #pragma unroll
        for (int i = 0; i < E_; i++) g_gates[t * E_ + i] = dec[i] * inv2;
    }
}

// ==================================================================
// 3) losses (exact fp32)
// ==================================================================
__global__ void losses_kernel(float* __restrict__ out_scalars) {
    __shared__ float gsum[F_][E_];
    __shared__ float cvf[F_], entf[F_];
    int tid = threadIdx.x;
    int f = tid >> 3, e = tid & 7;
    float s = 0.f;
    for (int b = 0; b < B_; b++) s += g_gates[(f * B_ + b) * E_ + e];
    gsum[f][e] = s;
    __syncthreads();
    if (tid < F_) {
        float mean = 0.f;
        #pragma unroll
        for (int i = 0; i < E_; i++) mean += gsum[tid][i];
        mean *= (1.f / E_);
        float ss = 0.f;
        #pragma unroll
        for (int i = 0; i < E_; i++) { float d = gsum[tid][i] - mean; ss += d * d; }
        float var = ss * (float)P_ / (float)(E_ * P_ - 1);
        cvf[tid] = var / (mean * mean + CV_EPS);
        float ent = 0.f;
        #pragma unroll
        for (int i = 0; i < E_; i++) {
            float g = gsum[tid][i] * (1.f / B_);
            ent += -g * logf(g + ENT_EPS);
        }
        entf[tid] = ent * (1.f / E_);
    }
    __syncthreads();
    if (tid == 0) {
        float a = 0.f, c = 0.f;
        for (int i = 0; i < F_; i++) { a += cvf[i]; c += entf[i]; }
        out_scalars[0] = a;
        out_scalars[1] = c;
    }
}

// ==================================================================
// 4) GEMM1 (mma.sync fp16): h = gelu(Xf @ W1t^T + b1), fp16 store
//    block 256M x 128N x 32K, 3-stage cp.async, 8 warps, warp 64x64
//    smem rows: 32 halves data @ PITCH=40 halves (80 B)
// ==================================================================
#define G1_STAGE_H ((256 + 128) * PITCH)           /* halves per stage */
#define G1_B_OFF_H (256 * PITCH)
#define G1_SMEM (3 * G1_STAGE_H * 2)
__global__ void __launch_bounds__(256, 1) gemm1_tc(const float* __restrict__ b1) {
    extern __shared__ __half smh[];
    const int tid = threadIdx.x;
    const int wid = tid >> 5, lane = tid & 31;
    const int g = lane >> 2, q = lane & 3;
    const int e = blockIdx.z;
    const int bm = blockIdx.y * 256, bn = blockIdx.x * 128;
    const int wm = (wid & 3) * 64, wn = (wid >> 2) * 64;
    const uint32_t smb = smem_u32(smh);

    const __half* gA = g_xf + (size_t)bm * S_;
    const __half* gB = g_w1t + ((size_t)e * H_ + bn) * S_;

    float acc[4][8][4];
    #pragma unroll
    for (int i = 0; i < 4; i++)
        #pragma unroll
        for (int j = 0; j < 8; j++)
            #pragma unroll
            for (int c = 0; c < 4; c++) acc[i][j][c] = 0.f;

    auto load_stage = [&](int kt, int buf) {
        const uint32_t sA = smb + (uint32_t)buf * (G1_STAGE_H * 2);
        const uint32_t sB = sA + G1_B_OFF_H * 2;
        const int k0 = kt * 32;
        #pragma unroll
        for (int i = 0; i < 4; i++) {          // A: 256 rows x 4 chunks(16B)
            int idx = tid + 256 * i;
            int r = idx >> 2, c = idx & 3;
            cp16(sA + (uint32_t)r * 80u + (uint32_t)c * 16u,
                 gA + (size_t)r * S_ + k0 + c * 8);
        }
        #pragma unroll
        for (int i = 0; i < 2; i++) {          // B: 128 rows x 4 chunks
            int idx = tid + 256 * i;
            int r = idx >> 2, c = idx & 3;
            cp16(sB + (uint32_t)r * 80u + (uint32_t)c * 16u,
                 gB + (size_t)r * S_ + k0 + c * 8);
        }
    };

    const int NKT = S_ / 32;   // 16
    #pragma unroll
    for (int s = 0; s < 3; s++) { load_stage(s, s); CP_COMMIT(); }

    for (int kt = 0; kt < NKT; kt++) {
        const int buf = kt % 3;
        CP_WAIT2();
        __syncthreads();
        const __half* As = smh + buf * G1_STAGE_H;
        const __half* Bs = As + G1_B_OFF_H;
        #pragma unroll
        for (int ks = 0; ks < 2; ks++) {       // two k16 slices
            const int kb = ks * 16;
            uint32_t a[4][4], b[8][2];
            #pragma unroll
            for (int i = 0; i < 4; i++) {
                int r = wm + i * 16 + g;
                a[i][0] = lds32(As, r * PITCH + kb + 2 * q);
                a[i][1] = lds32(As, (r + 8) * PITCH + kb + 2 * q);
                a[i][2] = lds32(As, r * PITCH + kb + 8 + 2 * q);
                a[i][3] = lds32(As, (r + 8) * PITCH + kb + 8 + 2 * q);
            }
            #pragma unroll
            for (int j = 0; j < 8; j++) {
                int n = wn + j * 8 + g;
                b[j][0] = lds32(Bs, n * PITCH + kb + 2 * q);
                b[j][1] = lds32(Bs, n * PITCH + kb + 8 + 2 * q);
            }
            #pragma unroll
            for (int i = 0; i < 4; i++)
                #pragma unroll
                for (int j = 0; j < 8; j++)
                    mma16(acc[i][j], a[i], b[j]);
        }
        __syncthreads();
        if (kt + 3 < NKT) load_stage(kt + 3, buf);
        CP_COMMIT();
    }

    // epilogue: bias + exact gelu, fp16 store
    const float* bias = b1 + (size_t)e * H_ + bn;
    #pragma unroll
    for (int i = 0; i < 4; i++) {
        int r0 = bm + wm + i * 16 + g;
        #pragma unroll
        for (int j = 0; j < 8; j++) {
            int col = wn + j * 8 + 2 * q;
            float bx = bias[col], by = bias[col + 1];
            __half2 o0 = __floats2half2_rn(gelu_f(acc[i][j][0] + bx),
                                           gelu_f(acc[i][j][1] + by));
            __half2 o1 = __floats2half2_rn(gelu_f(acc[i][j][2] + bx),
                                           gelu_f(acc[i][j][3] + by));
            *(__half2*)(g_h + ((size_t)e * T_ + r0) * H_ + bn + col) = o0;
            *(__half2*)(g_h + ((size_t)e * T_ + r0 + 8) * H_ + bn + col) = o1;
        }
    }
}

// ==================================================================
// 5) GEMM2 (mma.sync fp16): eo = h @ W2t^T
//    block 128M x 96N x 32K, 3-stage, 8 warps, warp 32x48
// ==================================================================
#define G2_STAGE_H ((128 + 96) * PITCH)
#define G2_B_OFF_H (128 * PITCH)
#define G2_SMEM (3 * G2_STAGE_H * 2)
__global__ void __launch_bounds__(256, 1) gemm2_tc(void) {
    extern __shared__ __half smh[];
    const int tid = threadIdx.x;
    const int wid = tid >> 5, lane = tid & 31;
    const int g = lane >> 2, q = lane & 3;
    const int e = blockIdx.z;
    const int bm = blockIdx.y * 128;
    const int wm = (wid & 3) * 32, wn = (wid >> 2) * 48;
    const uint32_t smb = smem_u32(smh);

    const __half* gA = g_h + ((size_t)e * T_ + bm) * H_;
    const __half* gB = g_w2t + (size_t)e * P_ * H_;

    float acc[2][6][4];
    #pragma unroll
    for (int i = 0; i < 2; i++)
        #pragma unroll
        for (int j = 0; j < 6; j++)
            #pragma unroll
            for (int c = 0; c < 4; c++) acc[i][j][c] = 0.f;

    auto load_stage = [&](int kt, int buf) {
        const uint32_t sA = smb + (uint32_t)buf * (G2_STAGE_H * 2);
        const uint32_t sB = sA + G2_B_OFF_H * 2;
        const int k0 = kt * 32;
        #pragma unroll
        for (int i = 0; i < 2; i++) {          // A: 128 rows x 4 chunks
            int idx = tid + 256 * i;
            int r = idx >> 2, c = idx & 3;
            cp16(sA + (uint32_t)r * 80u + (uint32_t)c * 16u,
                 gA + (size_t)r * H_ + k0 + c * 8);
        }
        #pragma unroll
        for (int i = 0; i < 2; i++) {          // B: 96 rows x 4 chunks = 384
            int idx = tid + 256 * i;
            if (idx < 384) {
                int r = idx >> 2, c = idx & 3;
                cp16(sB + (uint32_t)r * 80u + (uint32_t)c * 16u,
                     gB + (size_t)r * H_ + k0 + c * 8);
            }
        }
    };

    const int NKT = H_ / 32;   // 64
    #pragma unroll
    for (int s = 0; s < 3; s++) { load_stage(s, s); CP_COMMIT(); }

    for (int kt = 0; kt < NKT; kt++) {
        const int buf = kt % 3;
        CP_WAIT2();
        __syncthreads();
        const __half* As = smh + buf * G2_STAGE_H;
        const __half* Bs = As + G2_B_OFF_H;
        #pragma unroll
        for (int ks = 0; ks < 2; ks++) {
            const int kb = ks * 16;
            uint32_t a[2][4], b[6][2];
            #pragma unroll
            for (int i = 0; i < 2; i++) {
                int r = wm + i * 16 + g;
                a[i][0] = lds32(As, r * PITCH + kb + 2 * q);
                a[i][1] = lds32(As, (r + 8) * PITCH + kb + 2 * q);
                a[i][2] = lds32(As, r * PITCH + kb + 8 + 2 * q);
                a[i][3] = lds32(As, (r + 8) * PITCH + kb + 8 + 2 * q);
            }
            #pragma unroll
            for (int j = 0; j < 6; j++) {
                int n = wn + j * 8 + g;
                b[j][0] = lds32(Bs, n * PITCH + kb + 2 * q);
                b[j][1] = lds32(Bs, n * PITCH + kb + 8 + 2 * q);
            }
            #pragma unroll
            for (int i = 0; i < 2; i++)
                #pragma unroll
                for (int j = 0; j < 6; j++)
                    mma16(acc[i][j], a[i], b[j]);
        }
        __syncthreads();
        if (kt + 3 < NKT) load_stage(kt + 3, buf);
        CP_COMMIT();
    }

    #pragma unroll
    for (int i = 0; i < 2; i++) {
        int r0 = bm + wm + i * 16 + g;
        #pragma unroll
        for (int j = 0; j < 6; j++) {
            int col = wn + j * 8 + 2 * q;
            float2 o0, o1;
            o0.x = acc[i][j][0]; o0.y = acc[i][j][1];
            o1.x = acc[i][j][2]; o1.y = acc[i][j][3];
            *(float2*)(g_eo + ((size_t)e * T_ + r0) * P_ + col) = o0;
            *(float2*)(g_eo + ((size_t)e * T_ + r0 + 8) * P_ + col) = o1;
        }
    }
}

// ==================================================================
// 6) combine
// ==================================================================
__global__ void combine_kernel(const float* __restrict__ b2, float* __restrict__ out) {
    int idx = blockIdx.x * blockDim.x + threadIdx.x;
    if (idx >= T_ * P_) return;
    int t = idx / P_, p = idx - t * P_;
    int f = t / B_, b = t - f * B_;
    float r = 0.f;
    #pragma unroll
    for (int e = 0; e < E_; e++) {
        float v = b2[e * P_ + p] + g_eo[((size_t)e * T_ + t) * P_ + p];
        r += g_gates[t * E_ + e] * v;
    }
    out[((size_t)b * F_ + f) * P_ + p] = r;
}

// ==================================================================
extern "C" void kernel_launch(void* const* d_in, const int* in_sizes, int n_in,
                              void* d_out, int out_size) {
    const float* x  = (const float*)d_in[0];
    const float* te = (const float*)d_in[1];
    const float* Wg = (const float*)d_in[2];
    const float* bg = (const float*)d_in[3];
    const float* W1 = (const float*)d_in[4];
    const float* b1 = (const float*)d_in[5];
    const float* W2 = (const float*)d_in[6];
    const float* b2 = (const float*)d_in[7];
    float* out = (float*)d_out;

    cudaFuncSetAttribute(gemm1_tc, cudaFuncAttributeMaxDynamicSharedMemorySize, G1_SMEM);
    cudaFuncSetAttribute(gemm2_tc, cudaFuncAttributeMaxDynamicSharedMemorySize, G2_SMEM);

    prep_xf_kernel<<<T_, 128>>>(x);
    transpose_w1_kernel<<<dim3(H_ / 32, S_ / 32, E_), dim3(32, 8)>>>(W1);
    transpose_w2_kernel<<<dim3(P_ / 32, H_ / 32, E_), dim3(32, 8)>>>(W2);
    transpose_wg_kernel<<<16, 256>>>(Wg);
    gates_kernel<<<T_, 256>>>(te, bg);
    losses_kernel<<<1, 256>>>(out + (out_size - 2));
    gemm1_tc<<<dim3(H_ / 128, T_ / 256, E_), 256, G1_SMEM>>>(b1);
    gemm2_tc<<<dim3(1, T_ / 128, E_), 256, G2_SMEM>>>();
    combine_kernel<<<(T_ * P_ + 255) / 256, 256>>>(b2, out);
}

// round 5
// speedup vs baseline: 4.2775x; 1.0721x over previous
#include <cuda_runtime.h>
#include <cuda_fp16.h>
#include <math.h>
#include <stdint.h>

#define B_ 64
#define F_ 32
#define S_ 512
#define P_ 96
#define E_ 8
#define H_ 2048
#define T_ (F_*B_)   /* 2048 tokens */
#define ALPHA 10.0f
#define ENT_EPS 1e-8f
#define CV_EPS 1e-10f
#define KS2 2        /* gemm2 k-split */

// ---- scratch (device globals: allocation-free) ----
__device__ __half g_xf[(size_t)T_ * S_];           // 2 MB   token-major x (fp16)
__device__ __half g_w1t[(size_t)E_ * H_ * S_];     // 16.8MB W1^T [e][h][s] (fp16)
__device__ __half g_w2t[(size_t)E_ * P_ * H_];     // 3.1 MB W2^T [e][p][h] (fp16)
__device__ float  g_wgt[E_ * S_];                  // 16 KB  Wg^T [e][s]
__device__ float  g_gates[T_ * E_];                // 64 KB
__device__ __half g_h[(size_t)E_ * T_ * H_];       // 67 MB  gelu(x@W1+b1) (fp16)
__device__ float  g_eo[(size_t)E_ * KS2 * T_ * P_];// 12.6MB expert output partials

// ==================================================================
// helpers
// ==================================================================
__device__ __forceinline__ uint32_t smem_u32(const void* p) {
    uint32_t a;
    asm("{ .reg .u64 t; cvta.to.shared.u64 t, %1; cvt.u32.u64 %0, t; }"
        : "=r"(a) : "l"(p));
    return a;
}
__device__ __forceinline__ void cp16(uint32_t saddr, const void* gaddr) {
    asm volatile("cp.async.cg.shared.global [%0], [%1], 16;"
                 :: "r"(saddr), "l"(gaddr) : "memory");
}
#define CP_COMMIT() asm volatile("cp.async.commit_group;" ::: "memory")
#define CP_WAIT2()  asm volatile("cp.async.wait_group 2;" ::: "memory")

__device__ __forceinline__ void mma16(float* d, const uint32_t* a, const uint32_t* b) {
    asm volatile(
        "mma.sync.aligned.m16n8k16.row.col.f32.f16.f16.f32 "
        "{%0,%1,%2,%3}, {%4,%5,%6,%7}, {%8,%9}, {%0,%1,%2,%3};"
        : "+f"(d[0]), "+f"(d[1]), "+f"(d[2]), "+f"(d[3])
        : "r"(a[0]), "r"(a[1]), "r"(a[2]), "r"(a[3]), "r"(b[0]), "r"(b[1]));
}
__device__ __forceinline__ void ldsm4(uint32_t* r, uint32_t addr) {
    asm volatile("ldmatrix.sync.aligned.m8n8.x4.shared.b16 {%0,%1,%2,%3}, [%4];"
                 : "=r"(r[0]), "=r"(r[1]), "=r"(r[2]), "=r"(r[3]) : "r"(addr));
}
__device__ __forceinline__ float gelu_f(float v) {
    return 0.5f * v * (1.f + erff(v * 0.70710678118f));
}

// smem pitch: 40 halves (80 B) per 32-half row -> conflict-free (scalar + ldmatrix)
#define PITCH 40

// ==================================================================
// 1) x -> g_xf fp16 (blocks 0..2047); Wg^T (blocks 2048..2079)
// ==================================================================
__global__ void prep_xf_kernel(const float* __restrict__ x, const float* __restrict__ Wg) {
    int t = blockIdx.x;
    if (t < T_) {
        int f = t / B_, b = t - f * B_;
        const float4* src = (const float4*)(x + ((size_t)b * F_ + f) * S_);
        float4 v = src[threadIdx.x];
        __half2* dst = (__half2*)(g_xf + (size_t)t * S_) + threadIdx.x * 2;
        dst[0] = __floats2half2_rn(v.x, v.y);
        dst[1] = __floats2half2_rn(v.z, v.w);
    } else {
        int idx = (t - T_) * 128 + threadIdx.x;    // 32 blocks * 128 = 4096
        int e = idx >> 9, s = idx & 511;
        g_wgt[e * S_ + s] = Wg[s * E_ + e];
    }
}

// ==================================================================
// 1b) weight transposes (fp16 out)
// ==================================================================
__global__ void transpose_w1_kernel(const float* __restrict__ W1) {
    __shared__ float tile[32][33];
    int e = blockIdx.z;
    int h0 = blockIdx.x * 32, s0 = blockIdx.y * 32;
    int lx = threadIdx.x, ly = threadIdx.y;          // 32 x 8
    #pragma unroll
    for (int i = 0; i < 32; i += 8)
        tile[ly + i][lx] = W1[((size_t)e * S_ + s0 + ly + i) * H_ + h0 + lx];
    __syncthreads();
    #pragma unroll
    for (int i = 0; i < 32; i += 8)
        g_w1t[((size_t)e * H_ + h0 + ly + i) * S_ + s0 + lx] = __float2half_rn(tile[lx][ly + i]);
}
__global__ void transpose_w2_kernel(const float* __restrict__ W2) {
    __shared__ float tile[32][33];
    int e = blockIdx.z;
    int p0 = blockIdx.x * 32, h0 = blockIdx.y * 32;
    int lx = threadIdx.x, ly = threadIdx.y;
    #pragma unroll
    for (int i = 0; i < 32; i += 8)
        tile[ly + i][lx] = W2[((size_t)e * H_ + h0 + ly + i) * P_ + p0 + lx];
    __syncthreads();
    #pragma unroll
    for (int i = 0; i < 32; i += 8)
        g_w2t[((size_t)e * P_ + p0 + ly + i) * H_ + h0 + lx] = __float2half_rn(tile[lx][ly + i]);
}

// ==================================================================
// 2) gating network (exact fp32)
// ==================================================================
__global__ void gates_kernel(const float* __restrict__ te,
                             const float* __restrict__ bg) {
    int t = blockIdx.x;
    int f = t / B_, b = t - f * B_;
    __shared__ float srow[S_];
    __shared__ float slog[E_];
    const float* row = te + ((size_t)b * F_ + f) * S_;
    for (int s = threadIdx.x; s < S_; s += 256) srow[s] = row[s];
    __syncthreads();

    int w = threadIdx.x >> 5, lane = threadIdx.x & 31;
    const float* wrow = g_wgt + w * S_;
    float acc = 0.f;
    for (int s = lane; s < S_; s += 32) acc += srow[s] * wrow[s];
    #pragma unroll
    for (int o = 16; o > 0; o >>= 1) acc += __shfl_down_sync(0xffffffffu, acc, o);
    if (lane == 0) slog[w] = acc + bg[w];
    __syncthreads();

    if (threadIdx.x == 0) {
        float lg[E_];
        float m1 = -1e30f, m2 = -1e30f;
        #pragma unroll
        for (int i = 0; i < E_; i++) {
            float v = slog[i]; lg[i] = v;
            if (v > m1) { m2 = m1; m1 = v; } else if (v > m2) m2 = v;
        }
        float kth = m2;
        float sm[E_]; float se = 0.f;
        #pragma unroll
        for (int i = 0; i < E_; i++) { sm[i] = expf(lg[i] - m1); se += sm[i]; }
        float inv = 1.f / se;
        float dec[E_]; float mx2 = -1e30f;
        #pragma unroll
        for (int i = 0; i < E_; i++) {
            float smi = sm[i] * inv;
            float d = (lg[i] < kth) ? ALPHA * logf(smi + 1.f)
                                    : ALPHA * (expf(smi) - 1.f);
            dec[i] = d; if (d > mx2) mx2 = d;
        }
        float s2 = 0.f;
        #pragma unroll
        for (int i = 0; i < E_; i++) { dec[i] = expf(dec[i] - mx2); s2 += dec[i]; }
        float inv2 = 1.f / s2;
        #pragma unroll
        for (int i = 0; i < E_; i++) g_gates[t * E_ + i] = dec[i] * inv2;
    }
}

// ==================================================================
// 3) losses (exact fp32)
// ==================================================================
__global__ void losses_kernel(float* __restrict__ out_scalars) {
    __shared__ float gsum[F_][E_];
    __shared__ float cvf[F_], entf[F_];
    int tid = threadIdx.x;
    int f = tid >> 3, e = tid & 7;
    float s = 0.f;
    for (int b = 0; b < B_; b++) s += g_gates[(f * B_ + b) * E_ + e];
    gsum[f][e] = s;
    __syncthreads();
    if (tid < F_) {
        float mean = 0.f;
        #pragma unroll
        for (int i = 0; i < E_; i++) mean += gsum[tid][i];
        mean *= (1.f / E_);
        float ss = 0.f;
        #pragma unroll
        for (int i = 0; i < E_; i++) { float d = gsum[tid][i] - mean; ss += d * d; }
        float var = ss * (float)P_ / (float)(E_ * P_ - 1);
        cvf[tid] = var / (mean * mean + CV_EPS);
        float ent = 0.f;
        #pragma unroll
        for (int i = 0; i < E_; i++) {
            float g = gsum[tid][i] * (1.f / B_);
            ent += -g * logf(g + ENT_EPS);
        }
        entf[tid] = ent * (1.f / E_);
    }
    __syncthreads();
    if (tid == 0) {
        float a = 0.f, c = 0.f;
        for (int i = 0; i < F_; i++) { a += cvf[i]; c += entf[i]; }
        out_scalars[0] = a;
        out_scalars[1] = c;
    }
}

// ==================================================================
// 4) GEMM1 (HMMA + ldmatrix): h = gelu(Xf @ W1t^T + b1)
//    block 256M x 128N x 32K, 4-stage cp.async, single sync/iter,
//    8 warps, warp 64x64
// ==================================================================
#define G1_STAGE_H ((256 + 128) * PITCH)
#define G1_B_OFF (256 * PITCH * 2)                  /* bytes */
#define G1_STAGE_B (G1_STAGE_H * 2)                 /* bytes */
#define G1_SMEM (4 * G1_STAGE_B)
__global__ void __launch_bounds__(256, 1) gemm1_tc(const float* __restrict__ b1) {
    extern __shared__ __half smh[];
    const int tid = threadIdx.x;
    const int wid = tid >> 5, lane = tid & 31;
    const int g = lane >> 2, q = lane & 3;
    const int e = blockIdx.z;
    const int bm = blockIdx.y * 256, bn = blockIdx.x * 128;
    const int wm = (wid & 3) * 64, wn = (wid >> 2) * 64;
    const uint32_t smb = smem_u32(smh);

    const __half* gA = g_xf + (size_t)bm * S_;
    const __half* gB = g_w1t + ((size_t)e * H_ + bn) * S_;

    // ldmatrix per-lane offsets (bytes, within stage)
    uint32_t aoff[4], boff[4];
    {
        const int lrA = lane & 15, lcA = ((lane >> 4) & 1) * 8;
        #pragma unroll
        for (int i = 0; i < 4; i++)
            aoff[i] = (uint32_t)(((wm + i * 16 + lrA) * PITCH + lcA) * 2);
        const int lrB = (lane & 7) + ((lane & 16) >> 1), lcB = lane & 8;
        #pragma unroll
        for (int p = 0; p < 4; p++)
            boff[p] = (uint32_t)(G1_B_OFF + ((wn + p * 16 + lrB) * PITCH + lcB) * 2);
    }

    float acc[4][8][4];
    #pragma unroll
    for (int i = 0; i < 4; i++)
        #pragma unroll
        for (int j = 0; j < 8; j++)
            #pragma unroll
            for (int c = 0; c < 4; c++) acc[i][j][c] = 0.f;

    auto load_stage = [&](int kt, int buf) {
        const uint32_t sA = smb + (uint32_t)buf * G1_STAGE_B;
        const uint32_t sB = sA + G1_B_OFF;
        const int k0 = kt * 32;
        #pragma unroll
        for (int i = 0; i < 4; i++) {          // A: 256 rows x 4 chunks(16B)
            int idx = tid + 256 * i;
            int r = idx >> 2, c = idx & 3;
            cp16(sA + (uint32_t)r * 80u + (uint32_t)c * 16u,
                 gA + (size_t)r * S_ + k0 + c * 8);
        }
        #pragma unroll
        for (int i = 0; i < 2; i++) {          // B: 128 rows x 4 chunks
            int idx = tid + 256 * i;
            int r = idx >> 2, c = idx & 3;
            cp16(sB + (uint32_t)r * 80u + (uint32_t)c * 16u,
                 gB + (size_t)r * S_ + k0 + c * 8);
        }
    };

    const int NKT = S_ / 32;   // 16
    #pragma unroll
    for (int s = 0; s < 3; s++) { load_stage(s, s); CP_COMMIT(); }

    for (int kt = 0; kt < NKT; kt++) {
        CP_WAIT2();
        __syncthreads();
        if (kt + 3 < NKT) load_stage(kt + 3, (kt + 3) & 3);
        CP_COMMIT();
        const uint32_t sbase = smb + (uint32_t)(kt & 3) * G1_STAGE_B;
        #pragma unroll
        for (int ks = 0; ks < 2; ks++) {
            const uint32_t kboff = (uint32_t)(ks * 16 * 2);
            uint32_t a[4][4], bf[4][4];
            #pragma unroll
            for (int i = 0; i < 4; i++) ldsm4(a[i], sbase + aoff[i] + kboff);
            #pragma unroll
            for (int p = 0; p < 4; p++) ldsm4(bf[p], sbase + boff[p] + kboff);
            #pragma unroll
            for (int i = 0; i < 4; i++)
                #pragma unroll
                for (int p = 0; p < 4; p++) {
                    mma16(acc[i][2 * p + 0], a[i], &bf[p][0]);
                    mma16(acc[i][2 * p + 1], a[i], &bf[p][2]);
                }
        }
    }

    // epilogue: bias + exact gelu, fp16 store
    const float* bias = b1 + (size_t)e * H_ + bn;
    #pragma unroll
    for (int i = 0; i < 4; i++) {
        int r0 = bm + wm + i * 16 + g;
        #pragma unroll
        for (int j = 0; j < 8; j++) {
            int col = wn + j * 8 + 2 * q;
            float bx = bias[col], by = bias[col + 1];
            __half2 o0 = __floats2half2_rn(gelu_f(acc[i][j][0] + bx),
                                           gelu_f(acc[i][j][1] + by));
            __half2 o1 = __floats2half2_rn(gelu_f(acc[i][j][2] + bx),
                                           gelu_f(acc[i][j][3] + by));
            *(__half2*)(g_h + ((size_t)e * T_ + r0) * H_ + bn + col) = o0;
            *(__half2*)(g_h + ((size_t)e * T_ + r0 + 8) * H_ + bn + col) = o1;
        }
    }
}

// ==================================================================
// 5) GEMM2 (HMMA + ldmatrix, k-split x2): eo[ks] = h[:,ks] @ W2t^T
//    block 128M x 96N x 32K, 4-stage, 8 warps, warp 32x48
// ==================================================================
#define G2_STAGE_H ((128 + 96) * PITCH)
#define G2_B_OFF (128 * PITCH * 2)
#define G2_STAGE_B (G2_STAGE_H * 2)
#define G2_SMEM (4 * G2_STAGE_B)
__global__ void __launch_bounds__(256, 2) gemm2_tc(void) {
    extern __shared__ __half smh[];
    const int tid = threadIdx.x;
    const int wid = tid >> 5, lane = tid & 31;
    const int g = lane >> 2, q = lane & 3;
    const int e = blockIdx.z, ksp = blockIdx.x;
    const int bm = blockIdx.y * 128;
    const int k_base = ksp * (H_ / KS2);
    const int wm = (wid & 3) * 32, wn = (wid >> 2) * 48;
    const uint32_t smb = smem_u32(smh);

    const __half* gA = g_h + ((size_t)e * T_ + bm) * H_ + k_base;
    const __half* gB = g_w2t + (size_t)e * P_ * H_ + k_base;

    uint32_t aoff[2], boff[3];
    {
        const int lrA = lane & 15, lcA = ((lane >> 4) & 1) * 8;
        #pragma unroll
        for (int i = 0; i < 2; i++)
            aoff[i] = (uint32_t)(((wm + i * 16 + lrA) * PITCH + lcA) * 2);
        const int lrB = (lane & 7) + ((lane & 16) >> 1), lcB = lane & 8;
        #pragma unroll
        for (int p = 0; p < 3; p++)
            boff[p] = (uint32_t)(G2_B_OFF + ((wn + p * 16 + lrB) * PITCH + lcB) * 2);
    }

    float acc[2][6][4];
    #pragma unroll
    for (int i = 0; i < 2; i++)
        #pragma unroll
        for (int j = 0; j < 6; j++)
            #pragma unroll
            for (int c = 0; c < 4; c++) acc[i][j][c] = 0.f;

    auto load_stage = [&](int kt, int buf) {
        const uint32_t sA = smb + (uint32_t)buf * G2_STAGE_B;
        const uint32_t sB = sA + G2_B_OFF;
        const int k0 = kt * 32;
        #pragma unroll
        for (int i = 0; i < 2; i++) {          // A: 128 rows x 4 chunks
            int idx = tid + 256 * i;
            int r = idx >> 2, c = idx & 3;
            cp16(sA + (uint32_t)r * 80u + (uint32_t)c * 16u,
                 gA + (size_t)r * H_ + k0 + c * 8);
        }
        #pragma unroll
        for (int i = 0; i < 2; i++) {          // B: 96 rows x 4 chunks = 384
            int idx = tid + 256 * i;
            if (idx < 384) {
                int r = idx >> 2, c = idx & 3;
                cp16(sB + (uint32_t)r * 80u + (uint32_t)c * 16u,
                     gB + (size_t)r * H_ + k0 + c * 8);
            }
        }
    };

    const int NKT = (H_ / KS2) / 32;   // 32
    #pragma unroll
    for (int s = 0; s < 3; s++) { load_stage(s, s); CP_COMMIT(); }

    for (int kt = 0; kt < NKT; kt++) {
        CP_WAIT2();
        __syncthreads();
        if (kt + 3 < NKT) load_stage(kt + 3, (kt + 3) & 3);
        CP_COMMIT();
        const uint32_t sbase = smb + (uint32_t)(kt & 3) * G2_STAGE_B;
        #pragma unroll
        for (int ks = 0; ks < 2; ks++) {
            const uint32_t kboff = (uint32_t)(ks * 16 * 2);
            uint32_t a[2][4], bf[3][4];
            #pragma unroll
            for (int i = 0; i < 2; i++) ldsm4(a[i], sbase + aoff[i] + kboff);
            #pragma unroll
            for (int p = 0; p < 3; p++) ldsm4(bf[p], sbase + boff[p] + kboff);
            #pragma unroll
            for (int i = 0; i < 2; i++)
                #pragma unroll
                for (int p = 0; p < 3; p++) {
                    mma16(acc[i][2 * p + 0], a[i], &bf[p][0]);
                    mma16(acc[i][2 * p + 1], a[i], &bf[p][2]);
                }
        }
    }

    float* C = g_eo + (size_t)(e * KS2 + ksp) * T_ * P_;
    #pragma unroll
    for (int i = 0; i < 2; i++) {
        int r0 = bm + wm + i * 16 + g;
        #pragma unroll
        for (int j = 0; j < 6; j++) {
            int col = wn + j * 8 + 2 * q;
            float2 o0, o1;
            o0.x = acc[i][j][0]; o0.y = acc[i][j][1];
            o1.x = acc[i][j][2]; o1.y = acc[i][j][3];
            *(float2*)(C + (size_t)r0 * P_ + col) = o0;
            *(float2*)(C + (size_t)(r0 + 8) * P_ + col) = o1;
        }
    }
}

// ==================================================================
// 6) combine
// ==================================================================
__global__ void combine_kernel(const float* __restrict__ b2, float* __restrict__ out) {
    int idx = blockIdx.x * blockDim.x + threadIdx.x;
    if (idx >= T_ * P_) return;
    int t = idx / P_, p = idx - t * P_;
    int f = t / B_, b = t - f * B_;
    float r = 0.f;
    #pragma unroll
    for (int e = 0; e < E_; e++) {
        float v = b2[e * P_ + p]
                + g_eo[((size_t)(e * KS2 + 0) * T_ + t) * P_ + p]
                + g_eo[((size_t)(e * KS2 + 1) * T_ + t) * P_ + p];
        r += g_gates[t * E_ + e] * v;
    }
    out[((size_t)b * F_ + f) * P_ + p] = r;
}

// ==================================================================
extern "C" void kernel_launch(void* const* d_in, const int* in_sizes, int n_in,
                              void* d_out, int out_size) {
    const float* x  = (const float*)d_in[0];
    const float* te = (const float*)d_in[1];
    const float* Wg = (const float*)d_in[2];
    const float* bg = (const float*)d_in[3];
    const float* W1 = (const float*)d_in[4];
    const float* b1 = (const float*)d_in[5];
    const float* W2 = (const float*)d_in[6];
    const float* b2 = (const float*)d_in[7];
    float* out = (float*)d_out;

    cudaFuncSetAttribute(gemm1_tc, cudaFuncAttributeMaxDynamicSharedMemorySize, G1_SMEM);
    cudaFuncSetAttribute(gemm2_tc, cudaFuncAttributeMaxDynamicSharedMemorySize, G2_SMEM);

    prep_xf_kernel<<<T_ + 32, 128>>>(x, Wg);
    transpose_w1_kernel<<<dim3(H_ / 32, S_ / 32, E_), dim3(32, 8)>>>(W1);
    transpose_w2_kernel<<<dim3(P_ / 32, H_ / 32, E_), dim3(32, 8)>>>(W2);
    gates_kernel<<<T_, 256>>>(te, bg);
    losses_kernel<<<1, 256>>>(out + (out_size - 2));
    gemm1_tc<<<dim3(H_ / 128, T_ / 256, E_), 256, G1_SMEM>>>(b1);
    gemm2_tc<<<dim3(KS2, T_ / 128, E_), 256, G2_SMEM>>>();
    combine_kernel<<<(T_ * P_ + 255) / 256, 256>>>(b2, out);
}

// round 6
// speedup vs baseline: 4.6181x; 1.0796x over previous
#include <cuda_runtime.h>
#include <cuda_fp16.h>
#include <math.h>
#include <stdint.h>

#define B_ 64
#define F_ 32
#define S_ 512
#define P_ 96
#define E_ 8
#define H_ 2048
#define T_ (F_*B_)   /* 2048 tokens */
#define ALPHA 10.0f
#define ENT_EPS 1e-8f
#define CV_EPS 1e-10f
#define KS2 2        /* gemm2 k-split */

// ---- scratch (device globals: allocation-free) ----
__device__ __half g_xf[(size_t)T_ * S_];           // 2 MB   token-major x (fp16)
__device__ __half g_w1t[(size_t)E_ * H_ * S_];     // 16.8MB W1^T [e][h][s] (fp16)
__device__ __half g_w2t[(size_t)E_ * P_ * H_];     // 3.1 MB W2^T [e][p][h] (fp16)
__device__ float  g_gates[T_ * E_];                // 64 KB
__device__ __half g_h[(size_t)E_ * T_ * H_];       // 67 MB  gelu(x@W1+b1) (fp16)
__device__ float  g_eo[(size_t)E_ * KS2 * T_ * P_];// 12.6MB expert output partials

// ==================================================================
// helpers
// ==================================================================
__device__ __forceinline__ uint32_t smem_u32(const void* p) {
    uint32_t a;
    asm("{ .reg .u64 t; cvta.to.shared.u64 t, %1; cvt.u32.u64 %0, t; }"
        : "=r"(a) : "l"(p));
    return a;
}
__device__ __forceinline__ void cp16(uint32_t saddr, const void* gaddr) {
    asm volatile("cp.async.cg.shared.global [%0], [%1], 16;"
                 :: "r"(saddr), "l"(gaddr) : "memory");
}
#define CP_COMMIT() asm volatile("cp.async.commit_group;" ::: "memory")
#define CP_WAIT2()  asm volatile("cp.async.wait_group 2;" ::: "memory")

__device__ __forceinline__ void mma16(float* d, const uint32_t* a, const uint32_t* b) {
    asm volatile(
        "mma.sync.aligned.m16n8k16.row.col.f32.f16.f16.f32 "
        "{%0,%1,%2,%3}, {%4,%5,%6,%7}, {%8,%9}, {%0,%1,%2,%3};"
        : "+f"(d[0]), "+f"(d[1]), "+f"(d[2]), "+f"(d[3])
        : "r"(a[0]), "r"(a[1]), "r"(a[2]), "r"(a[3]), "r"(b[0]), "r"(b[1]));
}
__device__ __forceinline__ void ldsm4(uint32_t* r, uint32_t addr) {
    asm volatile("ldmatrix.sync.aligned.m8n8.x4.shared.b16 {%0,%1,%2,%3}, [%4];"
                 : "=r"(r[0]), "=r"(r[1]), "=r"(r[2]), "=r"(r[3]) : "r"(addr));
}
__device__ __forceinline__ float gelu_f(float v) {
    return 0.5f * v * (1.f + erff(v * 0.70710678118f));
}

// smem pitch: 40 halves (80 B) per 32-half row -> conflict-free (scalar + ldmatrix)
#define PITCH 40

// ==================================================================
// 1) x -> g_xf fp16
// ==================================================================
__global__ void prep_xf_kernel(const float* __restrict__ x) {
    int t = blockIdx.x;
    int f = t / B_, b = t - f * B_;
    const float4* src = (const float4*)(x + ((size_t)b * F_ + f) * S_);
    float4 v = src[threadIdx.x];
    __half2* dst = (__half2*)(g_xf + (size_t)t * S_) + threadIdx.x * 2;
    dst[0] = __floats2half2_rn(v.x, v.y);
    dst[1] = __floats2half2_rn(v.z, v.w);
}

// ==================================================================
// 1b) weight transposes (fp16 out)
// ==================================================================
__global__ void transpose_w1_kernel(const float* __restrict__ W1) {
    __shared__ float tile[32][33];
    int e = blockIdx.z;
    int h0 = blockIdx.x * 32, s0 = blockIdx.y * 32;
    int lx = threadIdx.x, ly = threadIdx.y;          // 32 x 8
    #pragma unroll
    for (int i = 0; i < 32; i += 8)
        tile[ly + i][lx] = W1[((size_t)e * S_ + s0 + ly + i) * H_ + h0 + lx];
    __syncthreads();
    #pragma unroll
    for (int i = 0; i < 32; i += 8)
        g_w1t[((size_t)e * H_ + h0 + ly + i) * S_ + s0 + lx] = __float2half_rn(tile[lx][ly + i]);
}
__global__ void transpose_w2_kernel(const float* __restrict__ W2) {
    __shared__ float tile[32][33];
    int e = blockIdx.z;
    int p0 = blockIdx.x * 32, h0 = blockIdx.y * 32;
    int lx = threadIdx.x, ly = threadIdx.y;
    #pragma unroll
    for (int i = 0; i < 32; i += 8)
        tile[ly + i][lx] = W2[((size_t)e * H_ + h0 + ly + i) * P_ + p0 + lx];
    __syncthreads();
    #pragma unroll
    for (int i = 0; i < 32; i += 8)
        g_w2t[((size_t)e * P_ + p0 + ly + i) * H_ + h0 + lx] = __float2half_rn(tile[lx][ly + i]);
}

// ==================================================================
// 2) gating network (exact fp32): 16 tokens per block, 128 threads.
//    thread = (expert, token) dot over S via float4 smem.
// ==================================================================
#define GT_TOK 16
#define GT_PITCH 516                     /* floats, float4-aligned, low-conflict */
#define GATES_SMEM ((GT_TOK + E_) * GT_PITCH * 4 + GT_TOK * E_ * 4)
__global__ void __launch_bounds__(128) gates_kernel(const float* __restrict__ te,
                                                    const float* __restrict__ Wg,
                                                    const float* __restrict__ bg) {
    extern __shared__ float sm[];
    float* s_te = sm;                               // [GT_TOK][GT_PITCH]
    float* s_wg = sm + GT_TOK * GT_PITCH;           // [E_][GT_PITCH]
    float* s_lg = s_wg + E_ * GT_PITCH;             // [GT_TOK][E_]
    const int tid = threadIdx.x;
    const int t0 = blockIdx.x * GT_TOK;

    // load 16 te rows (8 threads per row, float4)
    {
        int r = tid >> 3, j = tid & 7;
        int tok = t0 + r;
        int f = tok / B_, b = tok - f * B_;
        const float4* src = (const float4*)(te + ((size_t)b * F_ + f) * S_);
        float4* dst = (float4*)(s_te + r * GT_PITCH);
        #pragma unroll
        for (int k = 0; k < 16; k++) dst[j + 8 * k] = src[j + 8 * k];
    }
    // load Wg [s][e] -> s_wg[e][s]
    #pragma unroll
    for (int k = 0; k < 32; k++) {
        int idx = tid + 128 * k;                    // 4096
        float v = Wg[idx];
        s_wg[(idx & 7) * GT_PITCH + (idx >> 3)] = v;
    }
    __syncthreads();

    // dot: thread = (e, t)
    {
        int e = tid >> 4, t = tid & 15;
        const float4* a = (const float4*)(s_te + t * GT_PITCH);
        const float4* w = (const float4*)(s_wg + e * GT_PITCH);
        float acc = 0.f;
        #pragma unroll 8
        for (int i = 0; i < 128; i++) {
            float4 av = a[i], wv = w[i];
            acc += av.x * wv.x + av.y * wv.y + av.z * wv.z + av.w * wv.w;
        }
        s_lg[t * E_ + e] = acc + bg[e];
    }
    __syncthreads();

    if (tid < GT_TOK) {
        float lg[E_];
        float m1 = -1e30f, m2 = -1e30f;
        #pragma unroll
        for (int i = 0; i < E_; i++) {
            float v = s_lg[tid * E_ + i]; lg[i] = v;
            if (v > m1) { m2 = m1; m1 = v; } else if (v > m2) m2 = v;
        }
        float kth = m2;
        float smv[E_]; float se = 0.f;
        #pragma unroll
        for (int i = 0; i < E_; i++) { smv[i] = expf(lg[i] - m1); se += smv[i]; }
        float inv = 1.f / se;
        float dec[E_]; float mx2 = -1e30f;
        #pragma unroll
        for (int i = 0; i < E_; i++) {
            float smi = smv[i] * inv;
            float d = (lg[i] < kth) ? ALPHA * logf(smi + 1.f)
                                    : ALPHA * (expf(smi) - 1.f);
            dec[i] = d; if (d > mx2) mx2 = d;
        }
        float s2 = 0.f;
        #pragma unroll
        for (int i = 0; i < E_; i++) { dec[i] = expf(dec[i] - mx2); s2 += dec[i]; }
        float inv2 = 1.f / s2;
        #pragma unroll
        for (int i = 0; i < E_; i++) g_gates[(t0 + tid) * E_ + i] = dec[i] * inv2;
    }
}

// ==================================================================
// 3) losses (exact fp32)
// ==================================================================
__global__ void losses_kernel(float* __restrict__ out_scalars) {
    __shared__ float gsum[F_][E_];
    __shared__ float cvf[F_], entf[F_];
    int tid = threadIdx.x;
    int f = tid >> 3, e = tid & 7;
    float s = 0.f;
    for (int b = 0; b < B_; b++) s += g_gates[(f * B_ + b) * E_ + e];
    gsum[f][e] = s;
    __syncthreads();
    if (tid < F_) {
        float mean = 0.f;
        #pragma unroll
        for (int i = 0; i < E_; i++) mean += gsum[tid][i];
        mean *= (1.f / E_);
        float ss = 0.f;
        #pragma unroll
        for (int i = 0; i < E_; i++) { float d = gsum[tid][i] - mean; ss += d * d; }
        float var = ss * (float)P_ / (float)(E_ * P_ - 1);
        cvf[tid] = var / (mean * mean + CV_EPS);
        float ent = 0.f;
        #pragma unroll
        for (int i = 0; i < E_; i++) {
            float g = gsum[tid][i] * (1.f / B_);
            ent += -g * logf(g + ENT_EPS);
        }
        entf[tid] = ent * (1.f / E_);
    }
    __syncthreads();
    if (tid == 0) {
        float a = 0.f, c = 0.f;
        for (int i = 0; i < F_; i++) { a += cvf[i]; c += entf[i]; }
        out_scalars[0] = a;
        out_scalars[1] = c;
    }
}

// ==================================================================
// 4) GEMM1 (HMMA + ldmatrix): h = gelu(Xf @ W1t^T + b1)
//    block 128M x 128N x 32K, 4-stage, 8 warps (2m x 4n), warp 64x32
//    80 KB smem -> 2 CTAs/SM
// ==================================================================
#define G1_B_OFF (128 * PITCH * 2)                  /* bytes */
#define G1_STAGE_B (2 * 128 * PITCH * 2)            /* 20480 bytes */
#define G1_SMEM (4 * G1_STAGE_B)
__global__ void __launch_bounds__(256, 2) gemm1_tc(const float* __restrict__ b1) {
    extern __shared__ __half smh[];
    const int tid = threadIdx.x;
    const int wid = tid >> 5, lane = tid & 31;
    const int g = lane >> 2, q = lane & 3;
    const int e = blockIdx.z;
    const int bm = blockIdx.y * 128, bn = blockIdx.x * 128;
    const int wm = (wid & 1) * 64, wn = (wid >> 1) * 32;
    const uint32_t smb = smem_u32(smh);

    const __half* gA = g_xf + (size_t)bm * S_;
    const __half* gB = g_w1t + ((size_t)e * H_ + bn) * S_;

    uint32_t aoff[4], boff[2];
    {
        const int lrA = lane & 15, lcA = ((lane >> 4) & 1) * 8;
        #pragma unroll
        for (int i = 0; i < 4; i++)
            aoff[i] = (uint32_t)(((wm + i * 16 + lrA) * PITCH + lcA) * 2);
        const int lrB = (lane & 7) + ((lane & 16) >> 1), lcB = lane & 8;
        #pragma unroll
        for (int p = 0; p < 2; p++)
            boff[p] = (uint32_t)(G1_B_OFF + ((wn + p * 16 + lrB) * PITCH + lcB) * 2);
    }

    float acc[4][4][4];
    #pragma unroll
    for (int i = 0; i < 4; i++)
        #pragma unroll
        for (int j = 0; j < 4; j++)
            #pragma unroll
            for (int c = 0; c < 4; c++) acc[i][j][c] = 0.f;

    auto load_stage = [&](int kt, int buf) {
        const uint32_t sA = smb + (uint32_t)buf * G1_STAGE_B;
        const uint32_t sB = sA + G1_B_OFF;
        const int k0 = kt * 32;
        #pragma unroll
        for (int i = 0; i < 2; i++) {          // A: 128 rows x 4 chunks(16B)
            int idx = tid + 256 * i;
            int r = idx >> 2, c = idx & 3;
            cp16(sA + (uint32_t)r * 80u + (uint32_t)c * 16u,
                 gA + (size_t)r * S_ + k0 + c * 8);
        }
        #pragma unroll
        for (int i = 0; i < 2; i++) {          // B: 128 rows x 4 chunks
            int idx = tid + 256 * i;
            int r = idx >> 2, c = idx & 3;
            cp16(sB + (uint32_t)r * 80u + (uint32_t)c * 16u,
                 gB + (size_t)r * S_ + k0 + c * 8);
        }
    };

    const int NKT = S_ / 32;   // 16
    #pragma unroll
    for (int s = 0; s < 3; s++) { load_stage(s, s); CP_COMMIT(); }

    for (int kt = 0; kt < NKT; kt++) {
        CP_WAIT2();
        __syncthreads();
        if (kt + 3 < NKT) load_stage(kt + 3, (kt + 3) & 3);
        CP_COMMIT();
        const uint32_t sbase = smb + (uint32_t)(kt & 3) * G1_STAGE_B;
        #pragma unroll
        for (int ks = 0; ks < 2; ks++) {
            const uint32_t kboff = (uint32_t)(ks * 16 * 2);
            uint32_t a[4][4], bf[2][4];
            #pragma unroll
            for (int i = 0; i < 4; i++) ldsm4(a[i], sbase + aoff[i] + kboff);
            #pragma unroll
            for (int p = 0; p < 2; p++) ldsm4(bf[p], sbase + boff[p] + kboff);
            #pragma unroll
            for (int i = 0; i < 4; i++)
                #pragma unroll
                for (int p = 0; p < 2; p++) {
                    mma16(acc[i][2 * p + 0], a[i], &bf[p][0]);
                    mma16(acc[i][2 * p + 1], a[i], &bf[p][2]);
                }
        }
    }

    // epilogue: bias + exact gelu, fp16 store
    const float* bias = b1 + (size_t)e * H_ + bn;
    #pragma unroll
    for (int i = 0; i < 4; i++) {
        int r0 = bm + wm + i * 16 + g;
        #pragma unroll
        for (int j = 0; j < 4; j++) {
            int col = wn + j * 8 + 2 * q;
            float bx = bias[col], by = bias[col + 1];
            __half2 o0 = __floats2half2_rn(gelu_f(acc[i][j][0] + bx),
                                           gelu_f(acc[i][j][1] + by));
            __half2 o1 = __floats2half2_rn(gelu_f(acc[i][j][2] + bx),
                                           gelu_f(acc[i][j][3] + by));
            *(__half2*)(g_h + ((size_t)e * T_ + r0) * H_ + bn + col) = o0;
            *(__half2*)(g_h + ((size_t)e * T_ + r0 + 8) * H_ + bn + col) = o1;
        }
    }
}

// ==================================================================
// 5) GEMM2 (HMMA + ldmatrix, k-split x2): eo[ks] = h[:,ks] @ W2t^T
//    block 128M x 96N x 32K, 4-stage, 8 warps, warp 32x48
// ==================================================================
#define G2_STAGE_H ((128 + 96) * PITCH)
#define G2_B_OFF (128 * PITCH * 2)
#define G2_STAGE_B (G2_STAGE_H * 2)
#define G2_SMEM (4 * G2_STAGE_B)
__global__ void __launch_bounds__(256, 2) gemm2_tc(void) {
    extern __shared__ __half smh[];
    const int tid = threadIdx.x;
    const int wid = tid >> 5, lane = tid & 31;
    const int g = lane >> 2, q = lane & 3;
    const int e = blockIdx.z, ksp = blockIdx.x;
    const int bm = blockIdx.y * 128;
    const int k_base = ksp * (H_ / KS2);
    const int wm = (wid & 3) * 32, wn = (wid >> 2) * 48;
    const uint32_t smb = smem_u32(smh);

    const __half* gA = g_h + ((size_t)e * T_ + bm) * H_ + k_base;
    const __half* gB = g_w2t + (size_t)e * P_ * H_ + k_base;

    uint32_t aoff[2], boff[3];
    {
        const int lrA = lane & 15, lcA = ((lane >> 4) & 1) * 8;
        #pragma unroll
        for (int i = 0; i < 2; i++)
            aoff[i] = (uint32_t)(((wm + i * 16 + lrA) * PITCH + lcA) * 2);
        const int lrB = (lane & 7) + ((lane & 16) >> 1), lcB = lane & 8;
        #pragma unroll
        for (int p = 0; p < 3; p++)
            boff[p] = (uint32_t)(G2_B_OFF + ((wn + p * 16 + lrB) * PITCH + lcB) * 2);
    }

    float acc[2][6][4];
    #pragma unroll
    for (int i = 0; i < 2; i++)
        #pragma unroll
        for (int j = 0; j < 6; j++)
            #pragma unroll
            for (int c = 0; c < 4; c++) acc[i][j][c] = 0.f;

    auto load_stage = [&](int kt, int buf) {
        const uint32_t sA = smb + (uint32_t)buf * G2_STAGE_B;
        const uint32_t sB = sA + G2_B_OFF;
        const int k0 = kt * 32;
        #pragma unroll
        for (int i = 0; i < 2; i++) {          // A: 128 rows x 4 chunks
            int idx = tid + 256 * i;
            int r = idx >> 2, c = idx & 3;
            cp16(sA + (uint32_t)r * 80u + (uint32_t)c * 16u,
                 gA + (size_t)r * H_ + k0 + c * 8);
        }
        #pragma unroll
        for (int i = 0; i < 2; i++) {          // B: 96 rows x 4 chunks = 384
            int idx = tid + 256 * i;
            if (idx < 384) {
                int r = idx >> 2, c = idx & 3;
                cp16(sB + (uint32_t)r * 80u + (uint32_t)c * 16u,
                     gB + (size_t)r * H_ + k0 + c * 8);
            }
        }
    };

    const int NKT = (H_ / KS2) / 32;   // 32
    #pragma unroll
    for (int s = 0; s < 3; s++) { load_stage(s, s); CP_COMMIT(); }

    for (int kt = 0; kt < NKT; kt++) {
        CP_WAIT2();
        __syncthreads();
        if (kt + 3 < NKT) load_stage(kt + 3, (kt + 3) & 3);
        CP_COMMIT();
        const uint32_t sbase = smb + (uint32_t)(kt & 3) * G2_STAGE_B;
        #pragma unroll
        for (int ks = 0; ks < 2; ks++) {
            const uint32_t kboff = (uint32_t)(ks * 16 * 2);
            uint32_t a[2][4], bf[3][4];
            #pragma unroll
            for (int i = 0; i < 2; i++) ldsm4(a[i], sbase + aoff[i] + kboff);
            #pragma unroll
            for (int p = 0; p < 3; p++) ldsm4(bf[p], sbase + boff[p] + kboff);
            #pragma unroll
            for (int i = 0; i < 2; i++)
                #pragma unroll
                for (int p = 0; p < 3; p++) {
                    mma16(acc[i][2 * p + 0], a[i], &bf[p][0]);
                    mma16(acc[i][2 * p + 1], a[i], &bf[p][2]);
                }
        }
    }

    float* C = g_eo + (size_t)(e * KS2 + ksp) * T_ * P_;
    #pragma unroll
    for (int i = 0; i < 2; i++) {
        int r0 = bm + wm + i * 16 + g;
        #pragma unroll
        for (int j = 0; j < 6; j++) {
            int col = wn + j * 8 + 2 * q;
            float2 o0, o1;
            o0.x = acc[i][j][0]; o0.y = acc[i][j][1];
            o1.x = acc[i][j][2]; o1.y = acc[i][j][3];
            *(float2*)(C + (size_t)r0 * P_ + col) = o0;
            *(float2*)(C + (size_t)(r0 + 8) * P_ + col) = o1;
        }
    }
}

// ==================================================================
// 6) combine
// ==================================================================
__global__ void combine_kernel(const float* __restrict__ b2, float* __restrict__ out) {
    int idx = blockIdx.x * blockDim.x + threadIdx.x;
    if (idx >= T_ * P_) return;
    int t = idx / P_, p = idx - t * P_;
    int f = t / B_, b = t - f * B_;
    float r = 0.f;
    #pragma unroll
    for (int e = 0; e < E_; e++) {
        float v = b2[e * P_ + p]
                + g_eo[((size_t)(e * KS2 + 0) * T_ + t) * P_ + p]
                + g_eo[((size_t)(e * KS2 + 1) * T_ + t) * P_ + p];
        r += g_gates[t * E_ + e] * v;
    }
    out[((size_t)b * F_ + f) * P_ + p] = r;
}

// ==================================================================
extern "C" void kernel_launch(void* const* d_in, const int* in_sizes, int n_in,
                              void* d_out, int out_size) {
    const float* x  = (const float*)d_in[0];
    const float* te = (const float*)d_in[1];
    const float* Wg = (const float*)d_in[2];
    const float* bg = (const float*)d_in[3];
    const float* W1 = (const float*)d_in[4];
    const float* b1 = (const float*)d_in[5];
    const float* W2 = (const float*)d_in[6];
    const float* b2 = (const float*)d_in[7];
    float* out = (float*)d_out;

    cudaFuncSetAttribute(gemm1_tc, cudaFuncAttributeMaxDynamicSharedMemorySize, G1_SMEM);
    cudaFuncSetAttribute(gemm2_tc, cudaFuncAttributeMaxDynamicSharedMemorySize, G2_SMEM);
    cudaFuncSetAttribute(gates_kernel, cudaFuncAttributeMaxDynamicSharedMemorySize, GATES_SMEM);

    prep_xf_kernel<<<T_, 128>>>(x);
    transpose_w1_kernel<<<dim3(H_ / 32, S_ / 32, E_), dim3(32, 8)>>>(W1);
    transpose_w2_kernel<<<dim3(P_ / 32, H_ / 32, E_), dim3(32, 8)>>>(W2);
    gates_kernel<<<T_ / GT_TOK, 128, GATES_SMEM>>>(te, Wg, bg);
    losses_kernel<<<1, 256>>>(out + (out_size - 2));
    gemm1_tc<<<dim3(H_ / 128, T_ / 128, E_), 256, G1_SMEM>>>(b1);
    gemm2_tc<<<dim3(KS2, T_ / 128, E_), 256, G2_SMEM>>>();
    combine_kernel<<<(T_ * P_ + 255) / 256, 256>>>(b2, out);
}

// round 7
// speedup vs baseline: 4.7517x; 1.0289x over previous
#include <cuda_runtime.h>
#include <cuda_fp16.h>
#include <math.h>
#include <stdint.h>

#define B_ 64
#define F_ 32
#define S_ 512
#define P_ 96
#define E_ 8
#define H_ 2048
#define T_ (F_*B_)   /* 2048 tokens */
#define ALPHA 10.0f
#define ENT_EPS 1e-8f
#define CV_EPS 1e-10f
#define KS2 2        /* gemm2 k-split */

// ---- scratch (device globals: allocation-free) ----
__device__ __half g_xf[(size_t)T_ * S_];           // 2 MB   token-major x (fp16)
__device__ __half g_w1t[(size_t)E_ * H_ * S_];     // 16.8MB W1^T [e][h][s] (fp16)
__device__ __half g_w2t[(size_t)E_ * P_ * H_];     // 3.1 MB W2^T [e][p][h] (fp16)
__device__ float  g_gates[T_ * E_];                // 64 KB
__device__ __half g_h[(size_t)E_ * T_ * H_];       // 67 MB  gelu(x@W1+b1) (fp16)
__device__ float  g_eo[(size_t)E_ * KS2 * T_ * P_];// 12.6MB expert output partials

// ==================================================================
// helpers
// ==================================================================
__device__ __forceinline__ uint32_t smem_u32(const void* p) {
    uint32_t a;
    asm("{ .reg .u64 t; cvta.to.shared.u64 t, %1; cvt.u32.u64 %0, t; }"
        : "=r"(a) : "l"(p));
    return a;
}
__device__ __forceinline__ void cp16(uint32_t saddr, const void* gaddr) {
    asm volatile("cp.async.cg.shared.global [%0], [%1], 16;"
                 :: "r"(saddr), "l"(gaddr) : "memory");
}
#define CP_COMMIT() asm volatile("cp.async.commit_group;" ::: "memory")
#define CP_WAIT2()  asm volatile("cp.async.wait_group 2;" ::: "memory")

__device__ __forceinline__ void mma16(float* d, const uint32_t* a, const uint32_t* b) {
    asm volatile(
        "mma.sync.aligned.m16n8k16.row.col.f32.f16.f16.f32 "
        "{%0,%1,%2,%3}, {%4,%5,%6,%7}, {%8,%9}, {%0,%1,%2,%3};"
        : "+f"(d[0]), "+f"(d[1]), "+f"(d[2]), "+f"(d[3])
        : "r"(a[0]), "r"(a[1]), "r"(a[2]), "r"(a[3]), "r"(b[0]), "r"(b[1]));
}
__device__ __forceinline__ void ldsm4(uint32_t* r, uint32_t addr) {
    asm volatile("ldmatrix.sync.aligned.m8n8.x4.shared.b16 {%0,%1,%2,%3}, [%4];"
                 : "=r"(r[0]), "=r"(r[1]), "=r"(r[2]), "=r"(r[3]) : "r"(addr));
}
__device__ __forceinline__ float gelu_f(float v) {
    return 0.5f * v * (1.f + erff(v * 0.70710678118f));
}

// smem pitch: 40 halves (80 B) per 32-half row -> conflict-free (scalar + ldmatrix)
#define PITCH 40

// ==================================================================
// 1) fused prep: x->g_xf (blocks [0,1024)), W1^T (blocks [1024,9216)),
//    W2^T (blocks [9216,10752)).  256 threads each.
// ==================================================================
#define PREP_XF_BLKS 1024
#define PREP_W1_BLKS (64 * 16 * E_)     /* 8192 */
#define PREP_W2_BLKS (3 * 64 * E_)      /* 1536 */
#define PREP_TOTAL (PREP_XF_BLKS + PREP_W1_BLKS + PREP_W2_BLKS)
__global__ void __launch_bounds__(256) prep_all(const float* __restrict__ x,
                                                const float* __restrict__ W1,
                                                const float* __restrict__ W2) {
    __shared__ float tile[32][33];
    int bid = blockIdx.x;
    if (bid < PREP_XF_BLKS) {
        int t = bid * 2 + (threadIdx.x >> 7);
        int tl = threadIdx.x & 127;
        int f = t / B_, b = t - f * B_;
        const float4* src = (const float4*)(x + ((size_t)b * F_ + f) * S_);
        float4 v = src[tl];
        __half2* dst = (__half2*)(g_xf + (size_t)t * S_) + tl * 2;
        dst[0] = __floats2half2_rn(v.x, v.y);
        dst[1] = __floats2half2_rn(v.z, v.w);
    } else if (bid < PREP_XF_BLKS + PREP_W1_BLKS) {
        int i = bid - PREP_XF_BLKS;
        int e = i >> 10;                 // 64*16 per expert
        int r = i & 1023;
        int h0 = (r & 63) * 32, s0 = (r >> 6) * 32;
        int lx = threadIdx.x & 31, ly = threadIdx.x >> 5;    // 32 x 8
        #pragma unroll
        for (int k = 0; k < 32; k += 8)
            tile[ly + k][lx] = W1[((size_t)e * S_ + s0 + ly + k) * H_ + h0 + lx];
        __syncthreads();
        #pragma unroll
        for (int k = 0; k < 32; k += 8)
            g_w1t[((size_t)e * H_ + h0 + ly + k) * S_ + s0 + lx] = __float2half_rn(tile[lx][ly + k]);
    } else {
        int i = bid - PREP_XF_BLKS - PREP_W1_BLKS;
        int e = i / 192;
        int r = i % 192;
        int p0 = (r % 3) * 32, h0 = (r / 3) * 32;
        int lx = threadIdx.x & 31, ly = threadIdx.x >> 5;
        #pragma unroll
        for (int k = 0; k < 32; k += 8)
            tile[ly + k][lx] = W2[((size_t)e * H_ + h0 + ly + k) * P_ + p0 + lx];
        __syncthreads();
        #pragma unroll
        for (int k = 0; k < 32; k += 8)
            g_w2t[((size_t)e * P_ + p0 + ly + k) * H_ + h0 + lx] = __float2half_rn(tile[lx][ly + k]);
    }
}

// ==================================================================
// 2) gating (exact fp32): one warp per token, 8 warps/block, 256 blocks
//    Wg in smem pitch 9 (bank (9l+e) mod 32, conflict-free)
// ==================================================================
__global__ void __launch_bounds__(256) gates_kernel(const float* __restrict__ te,
                                                    const float* __restrict__ Wg,
                                                    const float* __restrict__ bg) {
    __shared__ float s_wg[S_ * 9];       // 18 KB
    const int tid = threadIdx.x;
    #pragma unroll
    for (int k = 0; k < 16; k++) {
        int idx = tid + 256 * k;         // 4096
        s_wg[(idx >> 3) * 9 + (idx & 7)] = Wg[idx];
    }
    __syncthreads();

    const int w = tid >> 5, lane = tid & 31;
    const int tok = blockIdx.x * 8 + w;
    const int f = tok / B_, b = tok - f * B_;
    const float* row = te + ((size_t)b * F_ + f) * S_;

    float acc[E_];
    #pragma unroll
    for (int e = 0; e < E_; e++) acc[e] = 0.f;
    #pragma unroll
    for (int c = 0; c < 16; c++) {
        float v = row[c * 32 + lane];
        const float* wp = s_wg + (c * 32 + lane) * 9;
        #pragma unroll
        for (int e = 0; e < E_; e++) acc[e] += v * wp[e];
    }
    #pragma unroll
    for (int e = 0; e < E_; e++)
        #pragma unroll
        for (int o = 16; o > 0; o >>= 1)
            acc[e] += __shfl_xor_sync(0xffffffffu, acc[e], o);

    if (lane == 0) {
        float lg[E_];
        float m1 = -1e30f, m2 = -1e30f;
        #pragma unroll
        for (int i = 0; i < E_; i++) {
            float v = acc[i] + bg[i]; lg[i] = v;
            if (v > m1) { m2 = m1; m1 = v; } else if (v > m2) m2 = v;
        }
        float kth = m2;
        float smv[E_]; float se = 0.f;
        #pragma unroll
        for (int i = 0; i < E_; i++) { smv[i] = expf(lg[i] - m1); se += smv[i]; }
        float inv = 1.f / se;
        float dec[E_]; float mx2 = -1e30f;
        #pragma unroll
        for (int i = 0; i < E_; i++) {
            float smi = smv[i] * inv;
            float d = (lg[i] < kth) ? ALPHA * logf(smi + 1.f)
                                    : ALPHA * (expf(smi) - 1.f);
            dec[i] = d; if (d > mx2) mx2 = d;
        }
        float s2 = 0.f;
        #pragma unroll
        for (int i = 0; i < E_; i++) { dec[i] = expf(dec[i] - mx2); s2 += dec[i]; }
        float inv2 = 1.f / s2;
        #pragma unroll
        for (int i = 0; i < E_; i++) g_gates[tok * E_ + i] = dec[i] * inv2;
    }
}

// ==================================================================
// 4) GEMM1 (HMMA + ldmatrix): h = gelu(Xf @ W1t^T + b1)
//    block 128M x 128N x 32K, 4-stage, 8 warps (2m x 4n), warp 64x32
//    80 KB smem -> 2 CTAs/SM
// ==================================================================
#define G1_B_OFF (128 * PITCH * 2)                  /* bytes */
#define G1_STAGE_B (2 * 128 * PITCH * 2)            /* 20480 bytes */
#define G1_SMEM (4 * G1_STAGE_B)
__global__ void __launch_bounds__(256, 2) gemm1_tc(const float* __restrict__ b1) {
    extern __shared__ __half smh[];
    const int tid = threadIdx.x;
    const int wid = tid >> 5, lane = tid & 31;
    const int g = lane >> 2, q = lane & 3;
    const int e = blockIdx.z;
    const int bm = blockIdx.y * 128, bn = blockIdx.x * 128;
    const int wm = (wid & 1) * 64, wn = (wid >> 1) * 32;
    const uint32_t smb = smem_u32(smh);

    const __half* gA = g_xf + (size_t)bm * S_;
    const __half* gB = g_w1t + ((size_t)e * H_ + bn) * S_;

    uint32_t aoff[4], boff[2];
    {
        const int lrA = lane & 15, lcA = ((lane >> 4) & 1) * 8;
        #pragma unroll
        for (int i = 0; i < 4; i++)
            aoff[i] = (uint32_t)(((wm + i * 16 + lrA) * PITCH + lcA) * 2);
        const int lrB = (lane & 7) + ((lane & 16) >> 1), lcB = lane & 8;
        #pragma unroll
        for (int p = 0; p < 2; p++)
            boff[p] = (uint32_t)(G1_B_OFF + ((wn + p * 16 + lrB) * PITCH + lcB) * 2);
    }

    float acc[4][4][4];
    #pragma unroll
    for (int i = 0; i < 4; i++)
        #pragma unroll
        for (int j = 0; j < 4; j++)
            #pragma unroll
            for (int c = 0; c < 4; c++) acc[i][j][c] = 0.f;

    auto load_stage = [&](int kt, int buf) {
        const uint32_t sA = smb + (uint32_t)buf * G1_STAGE_B;
        const uint32_t sB = sA + G1_B_OFF;
        const int k0 = kt * 32;
        #pragma unroll
        for (int i = 0; i < 2; i++) {
            int idx = tid + 256 * i;
            int r = idx >> 2, c = idx & 3;
            cp16(sA + (uint32_t)r * 80u + (uint32_t)c * 16u,
                 gA + (size_t)r * S_ + k0 + c * 8);
        }
        #pragma unroll
        for (int i = 0; i < 2; i++) {
            int idx = tid + 256 * i;
            int r = idx >> 2, c = idx & 3;
            cp16(sB + (uint32_t)r * 80u + (uint32_t)c * 16u,
                 gB + (size_t)r * S_ + k0 + c * 8);
        }
    };

    const int NKT = S_ / 32;   // 16
    #pragma unroll
    for (int s = 0; s < 3; s++) { load_stage(s, s); CP_COMMIT(); }

    for (int kt = 0; kt < NKT; kt++) {
        CP_WAIT2();
        __syncthreads();
        if (kt + 3 < NKT) load_stage(kt + 3, (kt + 3) & 3);
        CP_COMMIT();
        const uint32_t sbase = smb + (uint32_t)(kt & 3) * G1_STAGE_B;
        #pragma unroll
        for (int ks = 0; ks < 2; ks++) {
            const uint32_t kboff = (uint32_t)(ks * 16 * 2);
            uint32_t a[4][4], bf[2][4];
            #pragma unroll
            for (int i = 0; i < 4; i++) ldsm4(a[i], sbase + aoff[i] + kboff);
            #pragma unroll
            for (int p = 0; p < 2; p++) ldsm4(bf[p], sbase + boff[p] + kboff);
            #pragma unroll
            for (int i = 0; i < 4; i++)
                #pragma unroll
                for (int p = 0; p < 2; p++) {
                    mma16(acc[i][2 * p + 0], a[i], &bf[p][0]);
                    mma16(acc[i][2 * p + 1], a[i], &bf[p][2]);
                }
        }
    }

    const float* bias = b1 + (size_t)e * H_ + bn;
    #pragma unroll
    for (int i = 0; i < 4; i++) {
        int r0 = bm + wm + i * 16 + g;
        #pragma unroll
        for (int j = 0; j < 4; j++) {
            int col = wn + j * 8 + 2 * q;
            float bx = bias[col], by = bias[col + 1];
            __half2 o0 = __floats2half2_rn(gelu_f(acc[i][j][0] + bx),
                                           gelu_f(acc[i][j][1] + by));
            __half2 o1 = __floats2half2_rn(gelu_f(acc[i][j][2] + bx),
                                           gelu_f(acc[i][j][3] + by));
            *(__half2*)(g_h + ((size_t)e * T_ + r0) * H_ + bn + col) = o0;
            *(__half2*)(g_h + ((size_t)e * T_ + r0 + 8) * H_ + bn + col) = o1;
        }
    }
}

// ==================================================================
// 5) GEMM2 (HMMA + ldmatrix, k-split x2): eo[ks] = h[:,ks] @ W2t^T
//    block 128M x 96N x 32K, 4-stage, 8 warps, warp 32x48
// ==================================================================
#define G2_STAGE_H ((128 + 96) * PITCH)
#define G2_B_OFF (128 * PITCH * 2)
#define G2_STAGE_B (G2_STAGE_H * 2)
#define G2_SMEM (4 * G2_STAGE_B)
__global__ void __launch_bounds__(256, 2) gemm2_tc(void) {
    extern __shared__ __half smh[];
    const int tid = threadIdx.x;
    const int wid = tid >> 5, lane = tid & 31;
    const int g = lane >> 2, q = lane & 3;
    const int e = blockIdx.z, ksp = blockIdx.x;
    const int bm = blockIdx.y * 128;
    const int k_base = ksp * (H_ / KS2);
    const int wm = (wid & 3) * 32, wn = (wid >> 2) * 48;
    const uint32_t smb = smem_u32(smh);

    const __half* gA = g_h + ((size_t)e * T_ + bm) * H_ + k_base;
    const __half* gB = g_w2t + (size_t)e * P_ * H_ + k_base;

    uint32_t aoff[2], boff[3];
    {
        const int lrA = lane & 15, lcA = ((lane >> 4) & 1) * 8;
        #pragma unroll
        for (int i = 0; i < 2; i++)
            aoff[i] = (uint32_t)(((wm + i * 16 + lrA) * PITCH + lcA) * 2);
        const int lrB = (lane & 7) + ((lane & 16) >> 1), lcB = lane & 8;
        #pragma unroll
        for (int p = 0; p < 3; p++)
            boff[p] = (uint32_t)(G2_B_OFF + ((wn + p * 16 + lrB) * PITCH + lcB) * 2);
    }

    float acc[2][6][4];
    #pragma unroll
    for (int i = 0; i < 2; i++)
        #pragma unroll
        for (int j = 0; j < 6; j++)
            #pragma unroll
            for (int c = 0; c < 4; c++) acc[i][j][c] = 0.f;

    auto load_stage = [&](int kt, int buf) {
        const uint32_t sA = smb + (uint32_t)buf * G2_STAGE_B;
        const uint32_t sB = sA + G2_B_OFF;
        const int k0 = kt * 32;
        #pragma unroll
        for (int i = 0; i < 2; i++) {
            int idx = tid + 256 * i;
            int r = idx >> 2, c = idx & 3;
            cp16(sA + (uint32_t)r * 80u + (uint32_t)c * 16u,
                 gA + (size_t)r * H_ + k0 + c * 8);
        }
        #pragma unroll
        for (int i = 0; i < 2; i++) {
            int idx = tid + 256 * i;
            if (idx < 384) {
                int r = idx >> 2, c = idx & 3;
                cp16(sB + (uint32_t)r * 80u + (uint32_t)c * 16u,
                     gB + (size_t)r * H_ + k0 + c * 8);
            }
        }
    };

    const int NKT = (H_ / KS2) / 32;   // 32
    #pragma unroll
    for (int s = 0; s < 3; s++) { load_stage(s, s); CP_COMMIT(); }

    for (int kt = 0; kt < NKT; kt++) {
        CP_WAIT2();
        __syncthreads();
        if (kt + 3 < NKT) load_stage(kt + 3, (kt + 3) & 3);
        CP_COMMIT();
        const uint32_t sbase = smb + (uint32_t)(kt & 3) * G2_STAGE_B;
        #pragma unroll
        for (int ks = 0; ks < 2; ks++) {
            const uint32_t kboff = (uint32_t)(ks * 16 * 2);
            uint32_t a[2][4], bf[3][4];
            #pragma unroll
            for (int i = 0; i < 2; i++) ldsm4(a[i], sbase + aoff[i] + kboff);
            #pragma unroll
            for (int p = 0; p < 3; p++) ldsm4(bf[p], sbase + boff[p] + kboff);
            #pragma unroll
            for (int i = 0; i < 2; i++)
                #pragma unroll
                for (int p = 0; p < 3; p++) {
                    mma16(acc[i][2 * p + 0], a[i], &bf[p][0]);
                    mma16(acc[i][2 * p + 1], a[i], &bf[p][2]);
                }
        }
    }

    float* C = g_eo + (size_t)(e * KS2 + ksp) * T_ * P_;
    #pragma unroll
    for (int i = 0; i < 2; i++) {
        int r0 = bm + wm + i * 16 + g;
        #pragma unroll
        for (int j = 0; j < 6; j++) {
            int col = wn + j * 8 + 2 * q;
            float2 o0, o1;
            o0.x = acc[i][j][0]; o0.y = acc[i][j][1];
            o1.x = acc[i][j][2]; o1.y = acc[i][j][3];
            *(float2*)(C + (size_t)r0 * P_ + col) = o0;
            *(float2*)(C + (size_t)(r0 + 8) * P_ + col) = o1;
        }
    }
}

// ==================================================================
// 6) combine (blocks [0,768)) + losses (block 768)
// ==================================================================
__global__ void __launch_bounds__(256) combine_losses(const float* __restrict__ b2,
                                                      float* __restrict__ out,
                                                      float* __restrict__ out_scalars) {
    if (blockIdx.x < (T_ * P_) / 256) {
        int idx = blockIdx.x * 256 + threadIdx.x;
        int t = idx / P_, p = idx - t * P_;
        int f = t / B_, b = t - f * B_;
        float r = 0.f;
        #pragma unroll
        for (int e = 0; e < E_; e++) {
            float v = b2[e * P_ + p]
                    + g_eo[((size_t)(e * KS2 + 0) * T_ + t) * P_ + p]
                    + g_eo[((size_t)(e * KS2 + 1) * T_ + t) * P_ + p];
            r += g_gates[t * E_ + e] * v;
        }
        out[((size_t)b * F_ + f) * P_ + p] = r;
        return;
    }
    // losses block
    __shared__ float gsum[F_][E_];
    __shared__ float cvf[F_], entf[F_];
    int tid = threadIdx.x;
    int f = tid >> 3, e = tid & 7;
    float s = 0.f;
    for (int b = 0; b < B_; b++) s += g_gates[(f * B_ + b) * E_ + e];
    gsum[f][e] = s;
    __syncthreads();
    if (tid < F_) {
        float mean = 0.f;
        #pragma unroll
        for (int i = 0; i < E_; i++) mean += gsum[tid][i];
        mean *= (1.f / E_);
        float ss = 0.f;
        #pragma unroll
        for (int i = 0; i < E_; i++) { float d = gsum[tid][i] - mean; ss += d * d; }
        float var = ss * (float)P_ / (float)(E_ * P_ - 1);
        cvf[tid] = var / (mean * mean + CV_EPS);
        float ent = 0.f;
        #pragma unroll
        for (int i = 0; i < E_; i++) {
            float g = gsum[tid][i] * (1.f / B_);
            ent += -g * logf(g + ENT_EPS);
        }
        entf[tid] = ent * (1.f / E_);
    }
    __syncthreads();
    if (tid == 0) {
        float a = 0.f, c = 0.f;
        for (int i = 0; i < F_; i++) { a += cvf[i]; c += entf[i]; }
        out_scalars[0] = a;
        out_scalars[1] = c;
    }
}

// ==================================================================
extern "C" void kernel_launch(void* const* d_in, const int* in_sizes, int n_in,
                              void* d_out, int out_size) {
    const float* x  = (const float*)d_in[0];
    const float* te = (const float*)d_in[1];
    const float* Wg = (const float*)d_in[2];
    const float* bg = (const float*)d_in[3];
    const float* W1 = (const float*)d_in[4];
    const float* b1 = (const float*)d_in[5];
    const float* W2 = (const float*)d_in[6];
    const float* b2 = (const float*)d_in[7];
    float* out = (float*)d_out;

    cudaFuncSetAttribute(gemm1_tc, cudaFuncAttributeMaxDynamicSharedMemorySize, G1_SMEM);
    cudaFuncSetAttribute(gemm2_tc, cudaFuncAttributeMaxDynamicSharedMemorySize, G2_SMEM);

    prep_all<<<PREP_TOTAL, 256>>>(x, W1, W2);
    gates_kernel<<<T_ / 8, 256>>>(te, Wg, bg);
    gemm1_tc<<<dim3(H_ / 128, T_ / 128, E_), 256, G1_SMEM>>>(b1);
    gemm2_tc<<<dim3(KS2, T_ / 128, E_), 256, G2_SMEM>>>();
    combine_losses<<<(T_ * P_) / 256 + 1, 256>>>(b2, out, out + (out_size - 2));
}